// round 3
// baseline (speedup 1.0000x reference)
#include <cuda_runtime.h>
#include <cstdint>

#define NN 100000
#define EE 3200000
#define INC 128
#define HIDC 256
#define OUTC 64

static const int SCAN_CHUNK = 1024;
static const int SCAN_BLOCKS = (NN + SCAN_CHUNK - 1) / SCAN_CHUNK; // 98

// ---------------- scratch (static device arrays; no cudaMalloc) -------------
__device__ int   g_is64;
__device__ float g_deg[NN];
__device__ float g_dinv[NN];
__device__ int   g_count[NN];
__device__ int   g_rowstart[NN + 1];
__device__ int   g_cursor[NN];
__device__ int   g_blocksums[SCAN_BLOCKS];
__device__ int   g_csr_col[EE];
__device__ float g_csr_val[EE];
__device__ float g_T1a[(size_t)NN * INC];
__device__ float g_T2a[(size_t)NN * INC];
__device__ float g_H  [(size_t)NN * HIDC];
__device__ float g_T1b[(size_t)NN * HIDC];
__device__ float g_T2b[(size_t)NN * HIDC];

// ---------------- edge-index dtype helpers ----------------------------------
// Reference asks for int64 edge_index, but JAX w/o x64 silently emits int32.
// int32 data read as int64 packs two indices per word -> huge values.
__global__ void detect_kernel(const long long* __restrict__ ei) {
    if (threadIdx.x != 0 || blockIdx.x != 0) return;
    int is64 = 1;
    for (int i = 0; i < 4096; i++) {
        long long v = ei[i];
        if (v < 0 || v >= (long long)NN) { is64 = 0; break; }
    }
    g_is64 = is64;
}

// All index reads are clamped so a wrong assumption can NEVER produce an
// out-of-bounds address (it produces a wrong answer + diagnostics instead).
__device__ __forceinline__ int clampN(long long v) {
    if (v < 0) return 0;
    if (v >= NN) return NN - 1;
    return (int)v;
}
__device__ __forceinline__ int edge_row(const void* ei, int e) {
    long long v = g_is64 ? ((const long long*)ei)[e] : (long long)((const int*)ei)[e];
    return clampN(v);
}
__device__ __forceinline__ int edge_col(const void* ei, int e) {
    long long v = g_is64 ? ((const long long*)ei)[(size_t)EE + e]
                         : (long long)((const int*)ei)[(size_t)EE + e];
    return clampN(v);
}

// ---------------- small prep kernels ----------------------------------------
__global__ void zero_kernel() {
    int i = blockIdx.x * blockDim.x + threadIdx.x;
    if (i < NN) { g_deg[i] = 0.f; g_count[i] = 0; }
}

__global__ void deg_count_kernel(const void* __restrict__ ei,
                                 const float* __restrict__ ew) {
    int e = blockIdx.x * blockDim.x + threadIdx.x;
    if (e >= EE) return;
    int r = edge_row(ei, e);
    atomicAdd(&g_deg[r], ew[e]);
    atomicAdd(&g_count[r], 1);
}

__global__ void dinv_kernel() {
    int i = blockIdx.x * blockDim.x + threadIdx.x;
    if (i >= NN) return;
    float d = g_deg[i];
    g_dinv[i] = (d > 0.f) ? rsqrtf(d) : 0.f;
}

__global__ void scan_local_kernel() {
    __shared__ int sd[256];
    int b = blockIdx.x, t = threadIdx.x;
    int base = b * SCAN_CHUNK + t * 4;
    int v0 = 0, v1 = 0, v2 = 0, v3 = 0;
    if (base + 0 < NN) v0 = g_count[base + 0];
    if (base + 1 < NN) v1 = g_count[base + 1];
    if (base + 2 < NN) v2 = g_count[base + 2];
    if (base + 3 < NN) v3 = g_count[base + 3];
    int s = v0 + v1 + v2 + v3;
    sd[t] = s;
    __syncthreads();
    for (int off = 1; off < 256; off <<= 1) {
        int tmp = (t >= off) ? sd[t - off] : 0;
        __syncthreads();
        sd[t] += tmp;
        __syncthreads();
    }
    int excl = sd[t] - s;
    if (base + 0 < NN) g_rowstart[base + 0] = excl;
    excl += v0;
    if (base + 1 < NN) g_rowstart[base + 1] = excl;
    excl += v1;
    if (base + 2 < NN) g_rowstart[base + 2] = excl;
    excl += v2;
    if (base + 3 < NN) g_rowstart[base + 3] = excl;
    if (t == 255) g_blocksums[b] = sd[255];
}

__global__ void scan_blocks_kernel() {
    __shared__ int sd[128];
    int t = threadIdx.x;
    int v = (t < SCAN_BLOCKS) ? g_blocksums[t] : 0;
    sd[t] = v;
    __syncthreads();
    for (int off = 1; off < 128; off <<= 1) {
        int tmp = (t >= off) ? sd[t - off] : 0;
        __syncthreads();
        sd[t] += tmp;
        __syncthreads();
    }
    if (t < SCAN_BLOCKS) g_blocksums[t] = sd[t] - v;  // exclusive
}

__global__ void scan_add_kernel() {
    int b = blockIdx.x, t = threadIdx.x;
    int off = g_blocksums[b];
    int base = b * SCAN_CHUNK + t * 4;
#pragma unroll
    for (int j = 0; j < 4; j++) {
        int idx = base + j;
        if (idx < NN) {
            int rv = g_rowstart[idx] + off;
            g_rowstart[idx] = rv;
            g_cursor[idx]   = rv;
        }
    }
    if (b == 0 && t == 0) g_rowstart[NN] = EE;
}

__global__ void scatter_kernel(const void* __restrict__ ei,
                               const float* __restrict__ ew) {
    int e = blockIdx.x * blockDim.x + threadIdx.x;
    if (e >= EE) return;
    int r = edge_row(ei, e);
    int c = edge_col(ei, e);
    float w = ew[e];
    float nv = -(g_dinv[r] * w * g_dinv[c]);
    int pos = atomicAdd(&g_cursor[r], 1);
    if (pos < 0) pos = 0;
    if (pos >= EE) pos = EE - 1;       // safety: never out of bounds
    g_csr_col[pos] = c;
    g_csr_val[pos] = nv;
}

// ---------------- CSR SpMM: out = alpha * (L @ vin) + beta * sub ------------
template <int C>
__global__ void spmm_kernel(const float* __restrict__ vin,
                            float* __restrict__ vout,
                            const float* __restrict__ sub,
                            float alpha, float beta) {
    int w = (blockIdx.x * blockDim.x + threadIdx.x) >> 5;
    int lane = threadIdx.x & 31;
    if (w >= NN) return;
    int s = g_rowstart[w];
    int e = g_rowstart[w + 1];
    if (s < 0) s = 0;
    if (e > EE) e = EE;
    float4 a0 = make_float4(0.f, 0.f, 0.f, 0.f);
    float4 a1 = make_float4(0.f, 0.f, 0.f, 0.f);
    for (int base = s; base < e; base += 32) {
        int i = base + lane;
        int c = 0; float vv = 0.f;
        if (i < e) { c = g_csr_col[i]; vv = g_csr_val[i]; }
        int cnt = min(32, e - base);
        for (int j = 0; j < cnt; j++) {
            int   cc  = __shfl_sync(0xffffffffu, c, j);
            float val = __shfl_sync(0xffffffffu, vv, j);
            const float4* src = reinterpret_cast<const float4*>(vin) + (size_t)cc * (C / 4);
            float4 x0 = src[lane];
            a0.x = fmaf(val, x0.x, a0.x);
            a0.y = fmaf(val, x0.y, a0.y);
            a0.z = fmaf(val, x0.z, a0.z);
            a0.w = fmaf(val, x0.w, a0.w);
            if (C == 256) {
                float4 x1 = src[lane + 32];
                a1.x = fmaf(val, x1.x, a1.x);
                a1.y = fmaf(val, x1.y, a1.y);
                a1.z = fmaf(val, x1.z, a1.z);
                a1.w = fmaf(val, x1.w, a1.w);
            }
        }
    }
    float4* dst = reinterpret_cast<float4*>(vout) + (size_t)w * (C / 4);
    if (sub != nullptr) {
        const float4* sp = reinterpret_cast<const float4*>(sub) + (size_t)w * (C / 4);
        float4 s0 = sp[lane];
        a0.x = fmaf(beta, s0.x, alpha * a0.x);
        a0.y = fmaf(beta, s0.y, alpha * a0.y);
        a0.z = fmaf(beta, s0.z, alpha * a0.z);
        a0.w = fmaf(beta, s0.w, alpha * a0.w);
        if (C == 256) {
            float4 s1 = sp[lane + 32];
            a1.x = fmaf(beta, s1.x, alpha * a1.x);
            a1.y = fmaf(beta, s1.y, alpha * a1.y);
            a1.z = fmaf(beta, s1.z, alpha * a1.z);
            a1.w = fmaf(beta, s1.w, alpha * a1.w);
        }
    }
    dst[lane] = a0;
    if (C == 256) dst[lane + 32] = a1;
}

// ---------------- fused 3-term GEMM: out = [A0|A1|A2] @ Wflat + bias --------
template <int CIN, int COUT, bool RELU>
__global__ __launch_bounds__(256) void gemm3_kernel(
    const float* __restrict__ A0, const float* __restrict__ A1,
    const float* __restrict__ A2, const float* __restrict__ W,
    const float* __restrict__ bias, float* __restrict__ out) {
    const int BM = 128, BN = 64, BK = 8;
    __shared__ float As[BK][BM];
    __shared__ float Bs[BK][BN];
    int tid = threadIdx.x;
    int m0 = blockIdx.x * BM;
    int n0 = blockIdx.y * BN;
    int tx = tid & 15;
    int ty = tid >> 4;

    float acc[8][4];
#pragma unroll
    for (int i = 0; i < 8; i++)
#pragma unroll
        for (int j = 0; j < 4; j++) acc[i][j] = 0.f;

    const int KTOT = 3 * CIN;
    int mload = tid >> 1;
    int khalf = (tid & 1) * 4;
    int kbRow = tid >> 5;
    int nB    = (tid * 2) & 63;

    for (int k0 = 0; k0 < KTOT; k0 += BK) {
        int mat = k0 / CIN;
        const float* A = (mat == 0) ? A0 : ((mat == 1) ? A1 : A2);
        int kc = k0 - mat * CIN;

        int gm = m0 + mload;
        float4 av = make_float4(0.f, 0.f, 0.f, 0.f);
        if (gm < NN)
            av = *reinterpret_cast<const float4*>(A + (size_t)gm * CIN + kc + khalf);
        As[khalf + 0][mload] = av.x;
        As[khalf + 1][mload] = av.y;
        As[khalf + 2][mload] = av.z;
        As[khalf + 3][mload] = av.w;

        float2 wv = *reinterpret_cast<const float2*>(W + (size_t)(k0 + kbRow) * COUT + n0 + nB);
        Bs[kbRow][nB]     = wv.x;
        Bs[kbRow][nB + 1] = wv.y;
        __syncthreads();

#pragma unroll
        for (int kk = 0; kk < BK; kk++) {
            float4 aa0 = *reinterpret_cast<const float4*>(&As[kk][ty * 8]);
            float4 aa1 = *reinterpret_cast<const float4*>(&As[kk][ty * 8 + 4]);
            float4 bb  = *reinterpret_cast<const float4*>(&Bs[kk][tx * 4]);
            float am[8] = {aa0.x, aa0.y, aa0.z, aa0.w, aa1.x, aa1.y, aa1.z, aa1.w};
            float bn[4] = {bb.x, bb.y, bb.z, bb.w};
#pragma unroll
            for (int i = 0; i < 8; i++)
#pragma unroll
                for (int j = 0; j < 4; j++)
                    acc[i][j] = fmaf(am[i], bn[j], acc[i][j]);
        }
        __syncthreads();
    }

    float bv[4];
#pragma unroll
    for (int j = 0; j < 4; j++) bv[j] = bias[n0 + tx * 4 + j];

#pragma unroll
    for (int i = 0; i < 8; i++) {
        int gm = m0 + ty * 8 + i;
        if (gm < NN) {
            float4 r;
            r.x = acc[i][0] + bv[0];
            r.y = acc[i][1] + bv[1];
            r.z = acc[i][2] + bv[2];
            r.w = acc[i][3] + bv[3];
            if (RELU) {
                r.x = fmaxf(r.x, 0.f); r.y = fmaxf(r.y, 0.f);
                r.z = fmaxf(r.z, 0.f); r.w = fmaxf(r.w, 0.f);
            }
            *reinterpret_cast<float4*>(out + (size_t)gm * COUT + n0 + tx * 4) = r;
        }
    }
}

// ---------------- launch ----------------------------------------------------
extern "C" void kernel_launch(void* const* d_in, const int* in_sizes, int n_in,
                              void* d_out, int out_size) {
    // Identify inputs by element count (all counts are distinct) instead of
    // trusting positional order. Falls back to positional if a size is absent.
    const float* x  = nullptr; const void* ei = nullptr; const float* ew = nullptr;
    const float* W1 = nullptr; const float* b1 = nullptr;
    const float* W2 = nullptr; const float* b2 = nullptr;
    for (int i = 0; i < n_in; i++) {
        long long s = in_sizes[i];
        if      (s == (long long)NN * INC)        x  = (const float*)d_in[i];
        else if (s == 2LL * EE)                   ei = d_in[i];
        else if (s == (long long)EE)              ew = (const float*)d_in[i];
        else if (s == 3LL * INC * HIDC)           W1 = (const float*)d_in[i];
        else if (s == (long long)HIDC)            b1 = (const float*)d_in[i];
        else if (s == 3LL * HIDC * OUTC)          W2 = (const float*)d_in[i];
        else if (s == (long long)OUTC)            b2 = (const float*)d_in[i];
    }
    if (!x)  x  = (const float*)d_in[0];
    if (!ei) ei = d_in[1];
    if (!ew) ew = (const float*)d_in[2];
    if (!W1) W1 = (const float*)d_in[3];
    if (!b1) b1 = (const float*)d_in[4];
    if (!W2) W2 = (const float*)d_in[5];
    if (!b2) b2 = (const float*)d_in[6];
    float* out = (float*)d_out;

    void *pT1a, *pT2a, *pH, *pT1b, *pT2b;
    cudaGetSymbolAddress(&pT1a, g_T1a);
    cudaGetSymbolAddress(&pT2a, g_T2a);
    cudaGetSymbolAddress(&pH,   g_H);
    cudaGetSymbolAddress(&pT1b, g_T1b);
    cudaGetSymbolAddress(&pT2b, g_T2b);

    int nb = (NN + 255) / 256;
    int eb = (EE + 255) / 256;

    detect_kernel<<<1, 32>>>((const long long*)ei);
    zero_kernel<<<nb, 256>>>();
    deg_count_kernel<<<eb, 256>>>(ei, ew);
    dinv_kernel<<<nb, 256>>>();
    scan_local_kernel<<<SCAN_BLOCKS, 256>>>();
    scan_blocks_kernel<<<1, 128>>>();
    scan_add_kernel<<<SCAN_BLOCKS, 256>>>();
    scatter_kernel<<<eb, 256>>>(ei, ew);

    int sg = (NN * 32 + 255) / 256;  // warp per row

    // ---- layer 1: Tx0 = x ----
    spmm_kernel<128><<<sg, 256>>>(x, (float*)pT1a, nullptr, 1.f, 0.f);
    spmm_kernel<128><<<sg, 256>>>((float*)pT1a, (float*)pT2a, x, 2.f, -1.f);
    dim3 g1((NN + 127) / 128, HIDC / 64);
    gemm3_kernel<INC, HIDC, true><<<g1, 256>>>(
        x, (const float*)pT1a, (const float*)pT2a, W1, b1, (float*)pH);

    // ---- layer 2: Tx0 = h ----
    spmm_kernel<256><<<sg, 256>>>((const float*)pH, (float*)pT1b, nullptr, 1.f, 0.f);
    spmm_kernel<256><<<sg, 256>>>((const float*)pT1b, (float*)pT2b, (const float*)pH, 2.f, -1.f);
    dim3 g2((NN + 127) / 128, OUTC / 64);
    gemm3_kernel<HIDC, OUTC, false><<<g2, 256>>>(
        (const float*)pH, (const float*)pT1b, (const float*)pT2b, W2, b2, out);
}

// round 4
// speedup vs baseline: 1.2156x; 1.2156x over previous
#include <cuda_runtime.h>
#include <cstdint>

#define NN 100000
#define EE 3200000
#define INC 128
#define HIDC 256
#define OUTC 64

static const int SCAN_CHUNK = 1024;
static const int SCAN_BLOCKS = (NN + SCAN_CHUNK - 1) / SCAN_CHUNK; // 98

// ---------------- scratch (static device arrays; no cudaMalloc) -------------
__device__ int   g_is64;
__device__ float g_deg[NN];
__device__ float g_dinv[NN];
__device__ int   g_count[NN];
__device__ int   g_rowstart[NN + 1];
__device__ int   g_cursor[NN];
__device__ int   g_blocksums[SCAN_BLOCKS];
__device__ int   g_csr_col[EE];
__device__ float g_csr_val[EE];
__device__ float g_T1a[(size_t)NN * INC];
__device__ float g_T2a[(size_t)NN * INC];
__device__ float g_H  [(size_t)NN * HIDC];
__device__ float g_P0 [(size_t)NN * OUTC];
__device__ float g_P1 [(size_t)NN * OUTC];
__device__ float g_P2 [(size_t)NN * OUTC];
__device__ float g_Q1 [(size_t)NN * OUTC];
__device__ float g_Q2 [(size_t)NN * OUTC];
__device__ float g_W2t[HIDC * 3 * OUTC];   // [256][192]

// ---------------- edge-index dtype helpers ----------------------------------
__global__ void detect_kernel(const long long* __restrict__ ei) {
    if (threadIdx.x != 0 || blockIdx.x != 0) return;
    int is64 = 1;
    for (int i = 0; i < 4096; i++) {
        long long v = ei[i];
        if (v < 0 || v >= (long long)NN) { is64 = 0; break; }
    }
    g_is64 = is64;
}

__device__ __forceinline__ int clampN(long long v) {
    if (v < 0) return 0;
    if (v >= NN) return NN - 1;
    return (int)v;
}
__device__ __forceinline__ int edge_row(const void* ei, int e) {
    long long v = g_is64 ? ((const long long*)ei)[e] : (long long)((const int*)ei)[e];
    return clampN(v);
}
__device__ __forceinline__ int edge_col(const void* ei, int e) {
    long long v = g_is64 ? ((const long long*)ei)[(size_t)EE + e]
                         : (long long)((const int*)ei)[(size_t)EE + e];
    return clampN(v);
}

// ---------------- prep kernels ----------------------------------------------
__global__ void zero_kernel() {
    int i = blockIdx.x * blockDim.x + threadIdx.x;
    if (i < NN) { g_deg[i] = 0.f; g_count[i] = 0; }
}

__global__ void deg_count_kernel(const void* __restrict__ ei,
                                 const float* __restrict__ ew) {
    int e = blockIdx.x * blockDim.x + threadIdx.x;
    if (e >= EE) return;
    int r = edge_row(ei, e);
    atomicAdd(&g_deg[r], ew[e]);
    atomicAdd(&g_count[r], 1);
}

__global__ void dinv_kernel() {
    int i = blockIdx.x * blockDim.x + threadIdx.x;
    if (i >= NN) return;
    float d = g_deg[i];
    g_dinv[i] = (d > 0.f) ? rsqrtf(d) : 0.f;
}

__global__ void scan_local_kernel() {
    __shared__ int sd[256];
    int b = blockIdx.x, t = threadIdx.x;
    int base = b * SCAN_CHUNK + t * 4;
    int v0 = 0, v1 = 0, v2 = 0, v3 = 0;
    if (base + 0 < NN) v0 = g_count[base + 0];
    if (base + 1 < NN) v1 = g_count[base + 1];
    if (base + 2 < NN) v2 = g_count[base + 2];
    if (base + 3 < NN) v3 = g_count[base + 3];
    int s = v0 + v1 + v2 + v3;
    sd[t] = s;
    __syncthreads();
    for (int off = 1; off < 256; off <<= 1) {
        int tmp = (t >= off) ? sd[t - off] : 0;
        __syncthreads();
        sd[t] += tmp;
        __syncthreads();
    }
    int excl = sd[t] - s;
    if (base + 0 < NN) g_rowstart[base + 0] = excl;
    excl += v0;
    if (base + 1 < NN) g_rowstart[base + 1] = excl;
    excl += v1;
    if (base + 2 < NN) g_rowstart[base + 2] = excl;
    excl += v2;
    if (base + 3 < NN) g_rowstart[base + 3] = excl;
    if (t == 255) g_blocksums[b] = sd[255];
}

__global__ void scan_blocks_kernel() {
    __shared__ int sd[128];
    int t = threadIdx.x;
    int v = (t < SCAN_BLOCKS) ? g_blocksums[t] : 0;
    sd[t] = v;
    __syncthreads();
    for (int off = 1; off < 128; off <<= 1) {
        int tmp = (t >= off) ? sd[t - off] : 0;
        __syncthreads();
        sd[t] += tmp;
        __syncthreads();
    }
    if (t < SCAN_BLOCKS) g_blocksums[t] = sd[t] - v;  // exclusive
}

__global__ void scan_add_kernel() {
    int b = blockIdx.x, t = threadIdx.x;
    int off = g_blocksums[b];
    int base = b * SCAN_CHUNK + t * 4;
#pragma unroll
    for (int j = 0; j < 4; j++) {
        int idx = base + j;
        if (idx < NN) {
            int rv = g_rowstart[idx] + off;
            g_rowstart[idx] = rv;
            g_cursor[idx]   = rv;
        }
    }
    if (b == 0 && t == 0) g_rowstart[NN] = EE;
}

__global__ void scatter_kernel(const void* __restrict__ ei,
                               const float* __restrict__ ew) {
    int e = blockIdx.x * blockDim.x + threadIdx.x;
    if (e >= EE) return;
    int r = edge_row(ei, e);
    int c = edge_col(ei, e);
    float w = ew[e];
    float nv = -(g_dinv[r] * w * g_dinv[c]);
    int pos = atomicAdd(&g_cursor[r], 1);
    if (pos < 0) pos = 0;
    if (pos >= EE) pos = EE - 1;
    g_csr_col[pos] = c;
    g_csr_val[pos] = nv;
}

// W2 [3][256][64] -> W2t [256][192], W2t[c][k*64+j] = W2[k][c][j]
__global__ void transpose_w2_kernel(const float* __restrict__ W2) {
    int i = blockIdx.x * blockDim.x + threadIdx.x;
    if (i >= 3 * HIDC * OUTC) return;
    int k = i / (HIDC * OUTC);
    int rem = i - k * (HIDC * OUTC);
    int c = rem / OUTC;
    int j = rem - c * OUTC;
    g_W2t[c * (3 * OUTC) + k * OUTC + j] = W2[i];
}

// ---------------- CSR SpMM: out = alpha * (L @ vin) + beta * sub ------------
// warp-per-row; C=128 -> float4/lane, C=64 -> float2/lane
template <int C>
__global__ void spmm_kernel(const float* __restrict__ vin,
                            float* __restrict__ vout,
                            const float* __restrict__ sub,
                            float alpha, float beta) {
    int w = (blockIdx.x * blockDim.x + threadIdx.x) >> 5;
    int lane = threadIdx.x & 31;
    if (w >= NN) return;
    int s = g_rowstart[w];
    int e = g_rowstart[w + 1];
    if (s < 0) s = 0;
    if (e > EE) e = EE;

    if constexpr (C == 128) {
        float4 a0 = make_float4(0.f, 0.f, 0.f, 0.f);
        for (int base = s; base < e; base += 32) {
            int i = base + lane;
            int c = 0; float vv = 0.f;
            if (i < e) { c = g_csr_col[i]; vv = g_csr_val[i]; }
            int cnt = min(32, e - base);
            for (int j = 0; j < cnt; j++) {
                int   cc  = __shfl_sync(0xffffffffu, c, j);
                float val = __shfl_sync(0xffffffffu, vv, j);
                float4 x0 = reinterpret_cast<const float4*>(vin)[(size_t)cc * 32 + lane];
                a0.x = fmaf(val, x0.x, a0.x);
                a0.y = fmaf(val, x0.y, a0.y);
                a0.z = fmaf(val, x0.z, a0.z);
                a0.w = fmaf(val, x0.w, a0.w);
            }
        }
        float4* dst = reinterpret_cast<float4*>(vout) + (size_t)w * 32;
        if (sub != nullptr) {
            float4 s0 = reinterpret_cast<const float4*>(sub)[(size_t)w * 32 + lane];
            a0.x = fmaf(beta, s0.x, alpha * a0.x);
            a0.y = fmaf(beta, s0.y, alpha * a0.y);
            a0.z = fmaf(beta, s0.z, alpha * a0.z);
            a0.w = fmaf(beta, s0.w, alpha * a0.w);
        }
        dst[lane] = a0;
    } else {  // C == 64
        float2 a0 = make_float2(0.f, 0.f);
        for (int base = s; base < e; base += 32) {
            int i = base + lane;
            int c = 0; float vv = 0.f;
            if (i < e) { c = g_csr_col[i]; vv = g_csr_val[i]; }
            int cnt = min(32, e - base);
            for (int j = 0; j < cnt; j++) {
                int   cc  = __shfl_sync(0xffffffffu, c, j);
                float val = __shfl_sync(0xffffffffu, vv, j);
                float2 x0 = reinterpret_cast<const float2*>(vin)[(size_t)cc * 32 + lane];
                a0.x = fmaf(val, x0.x, a0.x);
                a0.y = fmaf(val, x0.y, a0.y);
            }
        }
        float2* dst = reinterpret_cast<float2*>(vout) + (size_t)w * 32;
        if (sub != nullptr) {
            float2 s0 = reinterpret_cast<const float2*>(sub)[(size_t)w * 32 + lane];
            a0.x = fmaf(beta, s0.x, alpha * a0.x);
            a0.y = fmaf(beta, s0.y, alpha * a0.y);
        }
        dst[lane] = a0;
    }
}

// ---------------- fused 3-term GEMM (layer 1): H = relu([x|T1|T2]@W1 + b1) --
template <int CIN, int COUT, bool RELU>
__global__ __launch_bounds__(256) void gemm3_kernel(
    const float* __restrict__ A0, const float* __restrict__ A1,
    const float* __restrict__ A2, const float* __restrict__ W,
    const float* __restrict__ bias, float* __restrict__ out) {
    const int BM = 128, BN = 64, BK = 8;
    __shared__ float As[BK][BM];
    __shared__ float Bs[BK][BN];
    int tid = threadIdx.x;
    int m0 = blockIdx.x * BM;
    int n0 = blockIdx.y * BN;
    int tx = tid & 15;
    int ty = tid >> 4;

    float acc[8][4];
#pragma unroll
    for (int i = 0; i < 8; i++)
#pragma unroll
        for (int j = 0; j < 4; j++) acc[i][j] = 0.f;

    const int KTOT = 3 * CIN;
    int mload = tid >> 1;
    int khalf = (tid & 1) * 4;
    int kbRow = tid >> 5;
    int nB    = (tid * 2) & 63;

    for (int k0 = 0; k0 < KTOT; k0 += BK) {
        int mat = k0 / CIN;
        const float* A = (mat == 0) ? A0 : ((mat == 1) ? A1 : A2);
        int kc = k0 - mat * CIN;

        int gm = m0 + mload;
        float4 av = make_float4(0.f, 0.f, 0.f, 0.f);
        if (gm < NN)
            av = *reinterpret_cast<const float4*>(A + (size_t)gm * CIN + kc + khalf);
        As[khalf + 0][mload] = av.x;
        As[khalf + 1][mload] = av.y;
        As[khalf + 2][mload] = av.z;
        As[khalf + 3][mload] = av.w;

        float2 wv = *reinterpret_cast<const float2*>(W + (size_t)(k0 + kbRow) * COUT + n0 + nB);
        Bs[kbRow][nB]     = wv.x;
        Bs[kbRow][nB + 1] = wv.y;
        __syncthreads();

#pragma unroll
        for (int kk = 0; kk < BK; kk++) {
            float4 aa0 = *reinterpret_cast<const float4*>(&As[kk][ty * 8]);
            float4 aa1 = *reinterpret_cast<const float4*>(&As[kk][ty * 8 + 4]);
            float4 bb  = *reinterpret_cast<const float4*>(&Bs[kk][tx * 4]);
            float am[8] = {aa0.x, aa0.y, aa0.z, aa0.w, aa1.x, aa1.y, aa1.z, aa1.w};
            float bn[4] = {bb.x, bb.y, bb.z, bb.w};
#pragma unroll
            for (int i = 0; i < 8; i++)
#pragma unroll
                for (int j = 0; j < 4; j++)
                    acc[i][j] = fmaf(am[i], bn[j], acc[i][j]);
        }
        __syncthreads();
    }

    float bv[4];
#pragma unroll
    for (int j = 0; j < 4; j++) bv[j] = bias[n0 + tx * 4 + j];

#pragma unroll
    for (int i = 0; i < 8; i++) {
        int gm = m0 + ty * 8 + i;
        if (gm < NN) {
            float4 r;
            r.x = acc[i][0] + bv[0];
            r.y = acc[i][1] + bv[1];
            r.z = acc[i][2] + bv[2];
            r.w = acc[i][3] + bv[3];
            if (RELU) {
                r.x = fmaxf(r.x, 0.f); r.y = fmaxf(r.y, 0.f);
                r.z = fmaxf(r.z, 0.f); r.w = fmaxf(r.w, 0.f);
            }
            *reinterpret_cast<float4*>(out + (size_t)gm * COUT + n0 + tx * 4) = r;
        }
    }
}

// ---------------- layer-2 projection: P_y = H @ W2t[:, 64y:64y+64] ---------
// A = H [NN][256], B = g_W2t [256][192]; blockIdx.y selects output buffer.
__global__ __launch_bounds__(256) void gemm1_kernel(
    const float* __restrict__ A,
    float* __restrict__ out0, float* __restrict__ out1, float* __restrict__ out2) {
    const int BM = 128, BK = 8;
    __shared__ float As[BK][BM];
    __shared__ float Bs[BK][64];
    int tid = threadIdx.x;
    int m0 = blockIdx.x * BM;
    int y  = blockIdx.y;
    int n0 = y * 64;
    float* out = (y == 0) ? out0 : ((y == 1) ? out1 : out2);
    int tx = tid & 15;
    int ty = tid >> 4;

    float acc[8][4];
#pragma unroll
    for (int i = 0; i < 8; i++)
#pragma unroll
        for (int j = 0; j < 4; j++) acc[i][j] = 0.f;

    int mload = tid >> 1;
    int khalf = (tid & 1) * 4;
    int kbRow = tid >> 5;
    int nB    = (tid * 2) & 63;

    for (int k0 = 0; k0 < HIDC; k0 += BK) {
        int gm = m0 + mload;
        float4 av = make_float4(0.f, 0.f, 0.f, 0.f);
        if (gm < NN)
            av = *reinterpret_cast<const float4*>(A + (size_t)gm * HIDC + k0 + khalf);
        As[khalf + 0][mload] = av.x;
        As[khalf + 1][mload] = av.y;
        As[khalf + 2][mload] = av.z;
        As[khalf + 3][mload] = av.w;

        float2 wv = *reinterpret_cast<const float2*>(
            g_W2t + (size_t)(k0 + kbRow) * (3 * OUTC) + n0 + nB);
        Bs[kbRow][nB]     = wv.x;
        Bs[kbRow][nB + 1] = wv.y;
        __syncthreads();

#pragma unroll
        for (int kk = 0; kk < BK; kk++) {
            float4 aa0 = *reinterpret_cast<const float4*>(&As[kk][ty * 8]);
            float4 aa1 = *reinterpret_cast<const float4*>(&As[kk][ty * 8 + 4]);
            float4 bb  = *reinterpret_cast<const float4*>(&Bs[kk][tx * 4]);
            float am[8] = {aa0.x, aa0.y, aa0.z, aa0.w, aa1.x, aa1.y, aa1.z, aa1.w};
            float bn[4] = {bb.x, bb.y, bb.z, bb.w};
#pragma unroll
            for (int i = 0; i < 8; i++)
#pragma unroll
                for (int j = 0; j < 4; j++)
                    acc[i][j] = fmaf(am[i], bn[j], acc[i][j]);
        }
        __syncthreads();
    }

#pragma unroll
    for (int i = 0; i < 8; i++) {
        int gm = m0 + ty * 8 + i;
        if (gm < NN) {
            float4 r = make_float4(acc[i][0], acc[i][1], acc[i][2], acc[i][3]);
            *reinterpret_cast<float4*>(out + (size_t)gm * OUTC + tx * 4) = r;
        }
    }
}

// ---------------- combine: S = P0 + Q1 - P2 + b2  (in-place into P0) -------
__global__ void combine_kernel(const float* __restrict__ b2) {
    int i = blockIdx.x * blockDim.x + threadIdx.x;   // float4 index
    const int total = NN * OUTC / 4;
    if (i >= total) return;
    int colv = (i & 15);  // 16 float4 per row of 64
    float4 p0 = reinterpret_cast<float4*>(g_P0)[i];
    float4 q1 = reinterpret_cast<float4*>(g_Q1)[i];
    float4 p2 = reinterpret_cast<float4*>(g_P2)[i];
    float4 bb = reinterpret_cast<const float4*>(b2)[colv];
    p0.x = p0.x + q1.x - p2.x + bb.x;
    p0.y = p0.y + q1.y - p2.y + bb.y;
    p0.z = p0.z + q1.z - p2.z + bb.z;
    p0.w = p0.w + q1.w - p2.w + bb.w;
    reinterpret_cast<float4*>(g_P0)[i] = p0;
}

// ---------------- launch ----------------------------------------------------
extern "C" void kernel_launch(void* const* d_in, const int* in_sizes, int n_in,
                              void* d_out, int out_size) {
    const float* x  = nullptr; const void* ei = nullptr; const float* ew = nullptr;
    const float* W1 = nullptr; const float* b1 = nullptr;
    const float* W2 = nullptr; const float* b2 = nullptr;
    for (int i = 0; i < n_in; i++) {
        long long s = in_sizes[i];
        if      (s == (long long)NN * INC)        x  = (const float*)d_in[i];
        else if (s == 2LL * EE)                   ei = d_in[i];
        else if (s == (long long)EE)              ew = (const float*)d_in[i];
        else if (s == 3LL * INC * HIDC)           W1 = (const float*)d_in[i];
        else if (s == (long long)HIDC)            b1 = (const float*)d_in[i];
        else if (s == 3LL * HIDC * OUTC)          W2 = (const float*)d_in[i];
        else if (s == (long long)OUTC)            b2 = (const float*)d_in[i];
    }
    if (!x)  x  = (const float*)d_in[0];
    if (!ei) ei = d_in[1];
    if (!ew) ew = (const float*)d_in[2];
    if (!W1) W1 = (const float*)d_in[3];
    if (!b1) b1 = (const float*)d_in[4];
    if (!W2) W2 = (const float*)d_in[5];
    if (!b2) b2 = (const float*)d_in[6];
    float* out = (float*)d_out;

    void *pT1a, *pT2a, *pH, *pP0, *pP1, *pP2, *pQ1, *pQ2;
    cudaGetSymbolAddress(&pT1a, g_T1a);
    cudaGetSymbolAddress(&pT2a, g_T2a);
    cudaGetSymbolAddress(&pH,   g_H);
    cudaGetSymbolAddress(&pP0,  g_P0);
    cudaGetSymbolAddress(&pP1,  g_P1);
    cudaGetSymbolAddress(&pP2,  g_P2);
    cudaGetSymbolAddress(&pQ1,  g_Q1);
    cudaGetSymbolAddress(&pQ2,  g_Q2);

    int nb = (NN + 255) / 256;
    int eb = (EE + 255) / 256;

    detect_kernel<<<1, 32>>>((const long long*)ei);
    zero_kernel<<<nb, 256>>>();
    deg_count_kernel<<<eb, 256>>>(ei, ew);
    dinv_kernel<<<nb, 256>>>();
    scan_local_kernel<<<SCAN_BLOCKS, 256>>>();
    scan_blocks_kernel<<<1, 128>>>();
    scan_add_kernel<<<SCAN_BLOCKS, 256>>>();
    scatter_kernel<<<eb, 256>>>(ei, ew);
    transpose_w2_kernel<<<(3 * HIDC * OUTC + 255) / 256, 256>>>(W2);

    int sg = (NN * 32 + 255) / 256;  // warp per row

    // ---- layer 1 ----
    spmm_kernel<128><<<sg, 256>>>(x, (float*)pT1a, nullptr, 1.f, 0.f);
    spmm_kernel<128><<<sg, 256>>>((float*)pT1a, (float*)pT2a, x, 2.f, -1.f);
    dim3 g1((NN + 127) / 128, HIDC / 64);
    gemm3_kernel<INC, HIDC, true><<<g1, 256>>>(
        x, (const float*)pT1a, (const float*)pT2a, W1, b1, (float*)pH);

    // ---- layer 2 (commuted: GEMM first, SpMM at width 64) ----
    dim3 g2((NN + 127) / 128, 3);
    gemm1_kernel<<<g2, 256>>>((const float*)pH, (float*)pP0, (float*)pP1, (float*)pP2);
    spmm_kernel<64><<<sg, 256>>>((const float*)pP1, (float*)pQ1, nullptr, 1.f, 0.f);
    spmm_kernel<64><<<sg, 256>>>((const float*)pP2, (float*)pQ2, nullptr, 1.f, 0.f);
    combine_kernel<<<(NN * OUTC / 4 + 255) / 256, 256>>>(b2);
    // out = 2*(L@Q2) + (P0 + Q1 - P2 + b2)
    spmm_kernel<64><<<sg, 256>>>((const float*)pQ2, out, (const float*)pP0, 2.f, 1.f);
}

// round 6
// speedup vs baseline: 1.2526x; 1.0304x over previous
#include <cuda_runtime.h>
#include <cuda_fp16.h>
#include <cstdint>

#define NN 100000
#define EE 3200000
#define INC 128
#define HIDC 256
#define OUTC 64

static const int SCAN_CHUNK = 1024;
static const int SCAN_BLOCKS = (NN + SCAN_CHUNK - 1) / SCAN_CHUNK; // 98

// ---------------- scratch (static device arrays; no cudaMalloc) -------------
__device__ int   g_is64;
__device__ float g_deg[NN];
__device__ float g_dinv[NN];
__device__ int   g_count[NN];
__device__ int   g_rowstart[NN + 1];
__device__ int   g_cursor[NN];
__device__ int   g_blocksums[SCAN_BLOCKS];
__device__ int   g_csr_col[EE];
__device__ float g_csr_val[EE];

__device__ __align__(16) __half g_xh [(size_t)NN * INC];
__device__ __align__(16) __half g_T1h[(size_t)NN * INC];
__device__ float g_T1 [(size_t)NN * INC];
__device__ float g_T2 [(size_t)NN * INC];
__device__ float g_H  [(size_t)NN * HIDC];
__device__ float g_P0 [(size_t)NN * OUTC];
__device__ __align__(16) __half g_P1h[(size_t)NN * OUTC];
__device__ __align__(16) __half g_P2h[(size_t)NN * OUTC];
__device__ float g_Q1 [(size_t)NN * OUTC];
__device__ __align__(16) __half g_Q2h[(size_t)NN * OUTC];
__device__ float g_W2t[HIDC * 3 * OUTC];   // [256][192]

// ---------------- edge-index dtype helpers ----------------------------------
__global__ void detect_kernel(const long long* __restrict__ ei) {
    if (threadIdx.x != 0 || blockIdx.x != 0) return;
    int is64 = 1;
    for (int i = 0; i < 4096; i++) {
        long long v = ei[i];
        if (v < 0 || v >= (long long)NN) { is64 = 0; break; }
    }
    g_is64 = is64;
}

__device__ __forceinline__ int clampN(long long v) {
    if (v < 0) return 0;
    if (v >= NN) return NN - 1;
    return (int)v;
}
__device__ __forceinline__ int edge_row(const void* ei, int e) {
    long long v = g_is64 ? ((const long long*)ei)[e] : (long long)((const int*)ei)[e];
    return clampN(v);
}
__device__ __forceinline__ int edge_col(const void* ei, int e) {
    long long v = g_is64 ? ((const long long*)ei)[(size_t)EE + e]
                         : (long long)((const int*)ei)[(size_t)EE + e];
    return clampN(v);
}

// ---------------- prep kernels ----------------------------------------------
__global__ void zero_kernel() {
    int i = blockIdx.x * blockDim.x + threadIdx.x;
    if (i < NN) { g_deg[i] = 0.f; g_count[i] = 0; }
}

__global__ void x2h_kernel(const float* __restrict__ x) {
    int i = blockIdx.x * blockDim.x + threadIdx.x;   // half2 index
    const int total = NN * INC / 2;
    if (i >= total) return;
    float2 f = reinterpret_cast<const float2*>(x)[i];
    reinterpret_cast<__half2*>(g_xh)[i] = __floats2half2_rn(f.x, f.y);
}

__global__ void deg_count_kernel(const void* __restrict__ ei,
                                 const float* __restrict__ ew) {
    int e = blockIdx.x * blockDim.x + threadIdx.x;
    if (e >= EE) return;
    int r = edge_row(ei, e);
    atomicAdd(&g_deg[r], ew[e]);
    atomicAdd(&g_count[r], 1);
}

__global__ void dinv_kernel() {
    int i = blockIdx.x * blockDim.x + threadIdx.x;
    if (i >= NN) return;
    float d = g_deg[i];
    g_dinv[i] = (d > 0.f) ? rsqrtf(d) : 0.f;
}

__global__ void scan_local_kernel() {
    __shared__ int sd[256];
    int b = blockIdx.x, t = threadIdx.x;
    int base = b * SCAN_CHUNK + t * 4;
    int v0 = 0, v1 = 0, v2 = 0, v3 = 0;
    if (base + 0 < NN) v0 = g_count[base + 0];
    if (base + 1 < NN) v1 = g_count[base + 1];
    if (base + 2 < NN) v2 = g_count[base + 2];
    if (base + 3 < NN) v3 = g_count[base + 3];
    int s = v0 + v1 + v2 + v3;
    sd[t] = s;
    __syncthreads();
    for (int off = 1; off < 256; off <<= 1) {
        int tmp = (t >= off) ? sd[t - off] : 0;
        __syncthreads();
        sd[t] += tmp;
        __syncthreads();
    }
    int excl = sd[t] - s;
    if (base + 0 < NN) g_rowstart[base + 0] = excl;
    excl += v0;
    if (base + 1 < NN) g_rowstart[base + 1] = excl;
    excl += v1;
    if (base + 2 < NN) g_rowstart[base + 2] = excl;
    excl += v2;
    if (base + 3 < NN) g_rowstart[base + 3] = excl;
    if (t == 255) g_blocksums[b] = sd[255];
}

__global__ void scan_blocks_kernel() {
    __shared__ int sd[128];
    int t = threadIdx.x;
    int v = (t < SCAN_BLOCKS) ? g_blocksums[t] : 0;
    sd[t] = v;
    __syncthreads();
    for (int off = 1; off < 128; off <<= 1) {
        int tmp = (t >= off) ? sd[t - off] : 0;
        __syncthreads();
        sd[t] += tmp;
        __syncthreads();
    }
    if (t < SCAN_BLOCKS) g_blocksums[t] = sd[t] - v;  // exclusive
}

__global__ void scan_add_kernel() {
    int b = blockIdx.x, t = threadIdx.x;
    int off = g_blocksums[b];
    int base = b * SCAN_CHUNK + t * 4;
#pragma unroll
    for (int j = 0; j < 4; j++) {
        int idx = base + j;
        if (idx < NN) {
            int rv = g_rowstart[idx] + off;
            g_rowstart[idx] = rv;
            g_cursor[idx]   = rv;
        }
    }
    if (b == 0 && t == 0) g_rowstart[NN] = EE;
}

__global__ void scatter_kernel(const void* __restrict__ ei,
                               const float* __restrict__ ew) {
    int e = blockIdx.x * blockDim.x + threadIdx.x;
    if (e >= EE) return;
    int r = edge_row(ei, e);
    int c = edge_col(ei, e);
    float w = ew[e];
    float nv = -(g_dinv[r] * w * g_dinv[c]);
    int pos = atomicAdd(&g_cursor[r], 1);
    if (pos < 0) pos = 0;
    if (pos >= EE) pos = EE - 1;
    g_csr_col[pos] = c;
    g_csr_val[pos] = nv;
}

// W2 [3][256][64] -> W2t [256][192]
__global__ void transpose_w2_kernel(const float* __restrict__ W2) {
    int i = blockIdx.x * blockDim.x + threadIdx.x;
    if (i >= 3 * HIDC * OUTC) return;
    int k = i / (HIDC * OUTC);
    int rem = i - k * (HIDC * OUTC);
    int c = rem / OUTC;
    int j = rem - c * OUTC;
    g_W2t[c * (3 * OUTC) + k * OUTC + j] = W2[i];
}

// ---------------- SpMM kernels (half gather, fp32 accumulate) ---------------
__device__ __forceinline__ void row_range(int w, int& s, int& e) {
    s = g_rowstart[w];
    e = g_rowstart[w + 1];
    if (s < 0) s = 0;
    if (e > EE) e = EE;
    if (e < s) e = s;
}

// T1 = L @ xh ; writes T1 (fp32, for GEMM) and T1h (half, for next gather)
__global__ void spmm1_kernel() {
    int w = (blockIdx.x * blockDim.x + threadIdx.x) >> 5;
    int lane = threadIdx.x & 31;
    if (w >= NN) return;
    int s, e; row_range(w, s, e);
    float4 a = make_float4(0.f, 0.f, 0.f, 0.f);
    const __half2* __restrict__ xh = reinterpret_cast<const __half2*>(g_xh);
    const int* __restrict__ cols = g_csr_col;
    const float* __restrict__ vals = g_csr_val;
    for (int base = s; base < e; base += 32) {
        int i = base + lane;
        int c = 0; float vv = 0.f;
        if (i < e) { c = cols[i]; vv = vals[i]; }
        int cnt = min(32, e - base);
        for (int j = 0; j < cnt; j++) {
            int   cc  = __shfl_sync(0xffffffffu, c, j);
            float val = __shfl_sync(0xffffffffu, vv, j);
            __half2 h0 = xh[(size_t)cc * 64 + lane * 2];
            __half2 h1 = xh[(size_t)cc * 64 + lane * 2 + 1];
            float2 f0 = __half22float2(h0);
            float2 f1 = __half22float2(h1);
            a.x = fmaf(val, f0.x, a.x);
            a.y = fmaf(val, f0.y, a.y);
            a.z = fmaf(val, f1.x, a.z);
            a.w = fmaf(val, f1.y, a.w);
        }
    }
    reinterpret_cast<float4*>(g_T1)[(size_t)w * 32 + lane] = a;
    __half2* t1h = reinterpret_cast<__half2*>(g_T1h);
    t1h[(size_t)w * 64 + lane * 2]     = __floats2half2_rn(a.x, a.y);
    t1h[(size_t)w * 64 + lane * 2 + 1] = __floats2half2_rn(a.z, a.w);
}

// T2 = 2 * (L @ T1h) - x   (x fp32, output fp32)
__global__ void spmm2_kernel(const float* __restrict__ x) {
    int w = (blockIdx.x * blockDim.x + threadIdx.x) >> 5;
    int lane = threadIdx.x & 31;
    if (w >= NN) return;
    int s, e; row_range(w, s, e);
    float4 a = make_float4(0.f, 0.f, 0.f, 0.f);
    const __half2* __restrict__ t1h = reinterpret_cast<const __half2*>(g_T1h);
    const int* __restrict__ cols = g_csr_col;
    const float* __restrict__ vals = g_csr_val;
    for (int base = s; base < e; base += 32) {
        int i = base + lane;
        int c = 0; float vv = 0.f;
        if (i < e) { c = cols[i]; vv = vals[i]; }
        int cnt = min(32, e - base);
        for (int j = 0; j < cnt; j++) {
            int   cc  = __shfl_sync(0xffffffffu, c, j);
            float val = __shfl_sync(0xffffffffu, vv, j);
            __half2 h0 = t1h[(size_t)cc * 64 + lane * 2];
            __half2 h1 = t1h[(size_t)cc * 64 + lane * 2 + 1];
            float2 f0 = __half22float2(h0);
            float2 f1 = __half22float2(h1);
            a.x = fmaf(val, f0.x, a.x);
            a.y = fmaf(val, f0.y, a.y);
            a.z = fmaf(val, f1.x, a.z);
            a.w = fmaf(val, f1.y, a.w);
        }
    }
    float4 xs = reinterpret_cast<const float4*>(x)[(size_t)w * 32 + lane];
    float4 r;
    r.x = 2.f * a.x - xs.x;
    r.y = 2.f * a.y - xs.y;
    r.z = 2.f * a.z - xs.z;
    r.w = 2.f * a.w - xs.w;
    reinterpret_cast<float4*>(g_T2)[(size_t)w * 32 + lane] = r;
}

// Q1 = L @ P1h (fp32 out), Q2h = half(L @ P2h)  — one CSR pass, two gathers
__global__ void spmm_dual_kernel() {
    int w = (blockIdx.x * blockDim.x + threadIdx.x) >> 5;
    int lane = threadIdx.x & 31;
    if (w >= NN) return;
    int s, e; row_range(w, s, e);
    float2 a1 = make_float2(0.f, 0.f);
    float2 a2 = make_float2(0.f, 0.f);
    const __half2* __restrict__ p1 = reinterpret_cast<const __half2*>(g_P1h);
    const __half2* __restrict__ p2 = reinterpret_cast<const __half2*>(g_P2h);
    const int* __restrict__ cols = g_csr_col;
    const float* __restrict__ vals = g_csr_val;
    for (int base = s; base < e; base += 32) {
        int i = base + lane;
        int c = 0; float vv = 0.f;
        if (i < e) { c = cols[i]; vv = vals[i]; }
        int cnt = min(32, e - base);
        for (int j = 0; j < cnt; j++) {
            int   cc  = __shfl_sync(0xffffffffu, c, j);
            float val = __shfl_sync(0xffffffffu, vv, j);
            float2 f1 = __half22float2(p1[(size_t)cc * 32 + lane]);
            float2 f2 = __half22float2(p2[(size_t)cc * 32 + lane]);
            a1.x = fmaf(val, f1.x, a1.x);
            a1.y = fmaf(val, f1.y, a1.y);
            a2.x = fmaf(val, f2.x, a2.x);
            a2.y = fmaf(val, f2.y, a2.y);
        }
    }
    reinterpret_cast<float2*>(g_Q1)[(size_t)w * 32 + lane] = a1;
    reinterpret_cast<__half2*>(g_Q2h)[(size_t)w * 32 + lane] = __floats2half2_rn(a2.x, a2.y);
}

// out = 2 * (L @ Q2h) + P0 + Q1 - P2h + b2    (fused combine)
__global__ void spmm_final_kernel(const float* __restrict__ b2,
                                  float* __restrict__ out) {
    int w = (blockIdx.x * blockDim.x + threadIdx.x) >> 5;
    int lane = threadIdx.x & 31;
    if (w >= NN) return;
    int s, e; row_range(w, s, e);
    float2 a = make_float2(0.f, 0.f);
    const __half2* __restrict__ q2 = reinterpret_cast<const __half2*>(g_Q2h);
    const int* __restrict__ cols = g_csr_col;
    const float* __restrict__ vals = g_csr_val;
    for (int base = s; base < e; base += 32) {
        int i = base + lane;
        int c = 0; float vv = 0.f;
        if (i < e) { c = cols[i]; vv = vals[i]; }
        int cnt = min(32, e - base);
        for (int j = 0; j < cnt; j++) {
            int   cc  = __shfl_sync(0xffffffffu, c, j);
            float val = __shfl_sync(0xffffffffu, vv, j);
            float2 f = __half22float2(q2[(size_t)cc * 32 + lane]);
            a.x = fmaf(val, f.x, a.x);
            a.y = fmaf(val, f.y, a.y);
        }
    }
    float2 p0 = reinterpret_cast<const float2*>(g_P0)[(size_t)w * 32 + lane];
    float2 q1 = reinterpret_cast<const float2*>(g_Q1)[(size_t)w * 32 + lane];
    float2 p2 = __half22float2(reinterpret_cast<const __half2*>(g_P2h)[(size_t)w * 32 + lane]);
    float2 bb = reinterpret_cast<const float2*>(b2)[lane];
    float2 r;
    r.x = 2.f * a.x + p0.x + q1.x - p2.x + bb.x;
    r.y = 2.f * a.y + p0.y + q1.y - p2.y + bb.y;
    reinterpret_cast<float2*>(out)[(size_t)w * 32 + lane] = r;
}

// ---------------- fused 3-term GEMM (layer 1): H = relu([x|T1|T2]@W1 + b1) --
template <int CIN, int COUT, bool RELU>
__global__ __launch_bounds__(256) void gemm3_kernel(
    const float* __restrict__ A0, const float* __restrict__ A1,
    const float* __restrict__ A2, const float* __restrict__ W,
    const float* __restrict__ bias, float* __restrict__ out) {
    const int BM = 128, BN = 64, BK = 8;
    __shared__ float As[BK][BM];
    __shared__ float Bs[BK][BN];
    int tid = threadIdx.x;
    int m0 = blockIdx.x * BM;
    int n0 = blockIdx.y * BN;
    int tx = tid & 15;
    int ty = tid >> 4;

    float acc[8][4];
#pragma unroll
    for (int i = 0; i < 8; i++)
#pragma unroll
        for (int j = 0; j < 4; j++) acc[i][j] = 0.f;

    const int KTOT = 3 * CIN;
    int mload = tid >> 1;
    int khalf = (tid & 1) * 4;
    int kbRow = tid >> 5;
    int nB    = (tid * 2) & 63;

    for (int k0 = 0; k0 < KTOT; k0 += BK) {
        int mat = k0 / CIN;
        const float* A = (mat == 0) ? A0 : ((mat == 1) ? A1 : A2);
        int kc = k0 - mat * CIN;

        int gm = m0 + mload;
        float4 av = make_float4(0.f, 0.f, 0.f, 0.f);
        if (gm < NN)
            av = *reinterpret_cast<const float4*>(A + (size_t)gm * CIN + kc + khalf);
        As[khalf + 0][mload] = av.x;
        As[khalf + 1][mload] = av.y;
        As[khalf + 2][mload] = av.z;
        As[khalf + 3][mload] = av.w;

        float2 wv = *reinterpret_cast<const float2*>(W + (size_t)(k0 + kbRow) * COUT + n0 + nB);
        Bs[kbRow][nB]     = wv.x;
        Bs[kbRow][nB + 1] = wv.y;
        __syncthreads();

#pragma unroll
        for (int kk = 0; kk < BK; kk++) {
            float4 aa0 = *reinterpret_cast<const float4*>(&As[kk][ty * 8]);
            float4 aa1 = *reinterpret_cast<const float4*>(&As[kk][ty * 8 + 4]);
            float4 bb  = *reinterpret_cast<const float4*>(&Bs[kk][tx * 4]);
            float am[8] = {aa0.x, aa0.y, aa0.z, aa0.w, aa1.x, aa1.y, aa1.z, aa1.w};
            float bn[4] = {bb.x, bb.y, bb.z, bb.w};
#pragma unroll
            for (int i = 0; i < 8; i++)
#pragma unroll
                for (int j = 0; j < 4; j++)
                    acc[i][j] = fmaf(am[i], bn[j], acc[i][j]);
        }
        __syncthreads();
    }

    float bv[4];
#pragma unroll
    for (int j = 0; j < 4; j++) bv[j] = bias[n0 + tx * 4 + j];

#pragma unroll
    for (int i = 0; i < 8; i++) {
        int gm = m0 + ty * 8 + i;
        if (gm < NN) {
            float4 r;
            r.x = acc[i][0] + bv[0];
            r.y = acc[i][1] + bv[1];
            r.z = acc[i][2] + bv[2];
            r.w = acc[i][3] + bv[3];
            if (RELU) {
                r.x = fmaxf(r.x, 0.f); r.y = fmaxf(r.y, 0.f);
                r.z = fmaxf(r.z, 0.f); r.w = fmaxf(r.w, 0.f);
            }
            *reinterpret_cast<float4*>(out + (size_t)gm * COUT + n0 + tx * 4) = r;
        }
    }
}

// ---------------- layer-2 projection: P_y = H @ W2t[:, 64y:64y+64] ---------
// y=0 -> fp32 P0; y=1,2 -> half P1h/P2h
__global__ __launch_bounds__(256) void gemm1_kernel(
    const float* __restrict__ A,
    float* __restrict__ out0, __half* __restrict__ out1, __half* __restrict__ out2) {
    const int BM = 128, BK = 8;
    __shared__ float As[BK][BM];
    __shared__ float Bs[BK][64];
    int tid = threadIdx.x;
    int m0 = blockIdx.x * BM;
    int y  = blockIdx.y;
    int n0 = y * 64;
    int tx = tid & 15;
    int ty = tid >> 4;

    float acc[8][4];
#pragma unroll
    for (int i = 0; i < 8; i++)
#pragma unroll
        for (int j = 0; j < 4; j++) acc[i][j] = 0.f;

    int mload = tid >> 1;
    int khalf = (tid & 1) * 4;
    int kbRow = tid >> 5;
    int nB    = (tid * 2) & 63;

    for (int k0 = 0; k0 < HIDC; k0 += BK) {
        int gm = m0 + mload;
        float4 av = make_float4(0.f, 0.f, 0.f, 0.f);
        if (gm < NN)
            av = *reinterpret_cast<const float4*>(A + (size_t)gm * HIDC + k0 + khalf);
        As[khalf + 0][mload] = av.x;
        As[khalf + 1][mload] = av.y;
        As[khalf + 2][mload] = av.z;
        As[khalf + 3][mload] = av.w;

        float2 wv = *reinterpret_cast<const float2*>(
            g_W2t + (size_t)(k0 + kbRow) * (3 * OUTC) + n0 + nB);
        Bs[kbRow][nB]     = wv.x;
        Bs[kbRow][nB + 1] = wv.y;
        __syncthreads();

#pragma unroll
        for (int kk = 0; kk < BK; kk++) {
            float4 aa0 = *reinterpret_cast<const float4*>(&As[kk][ty * 8]);
            float4 aa1 = *reinterpret_cast<const float4*>(&As[kk][ty * 8 + 4]);
            float4 bb  = *reinterpret_cast<const float4*>(&Bs[kk][tx * 4]);
            float am[8] = {aa0.x, aa0.y, aa0.z, aa0.w, aa1.x, aa1.y, aa1.z, aa1.w};
            float bn[4] = {bb.x, bb.y, bb.z, bb.w};
#pragma unroll
            for (int i = 0; i < 8; i++)
#pragma unroll
                for (int j = 0; j < 4; j++)
                    acc[i][j] = fmaf(am[i], bn[j], acc[i][j]);
        }
        __syncthreads();
    }

#pragma unroll
    for (int i = 0; i < 8; i++) {
        int gm = m0 + ty * 8 + i;
        if (gm < NN) {
            if (y == 0) {
                float4 r = make_float4(acc[i][0], acc[i][1], acc[i][2], acc[i][3]);
                *reinterpret_cast<float4*>(out0 + (size_t)gm * OUTC + tx * 4) = r;
            } else {
                __half* oh = (y == 1) ? out1 : out2;
                __half2 h01 = __floats2half2_rn(acc[i][0], acc[i][1]);
                __half2 h23 = __floats2half2_rn(acc[i][2], acc[i][3]);
                __half2* dst = reinterpret_cast<__half2*>(oh + (size_t)gm * OUTC + tx * 4);
                dst[0] = h01;
                dst[1] = h23;
            }
        }
    }
}

// ---------------- launch ----------------------------------------------------
extern "C" void kernel_launch(void* const* d_in, const int* in_sizes, int n_in,
                              void* d_out, int out_size) {
    const float* x  = nullptr; const void* ei = nullptr; const float* ew = nullptr;
    const float* W1 = nullptr; const float* b1 = nullptr;
    const float* W2 = nullptr; const float* b2 = nullptr;
    for (int i = 0; i < n_in; i++) {
        long long s = in_sizes[i];
        if      (s == (long long)NN * INC)        x  = (const float*)d_in[i];
        else if (s == 2LL * EE)                   ei = d_in[i];
        else if (s == (long long)EE)              ew = (const float*)d_in[i];
        else if (s == 3LL * INC * HIDC)           W1 = (const float*)d_in[i];
        else if (s == (long long)HIDC)            b1 = (const float*)d_in[i];
        else if (s == 3LL * HIDC * OUTC)          W2 = (const float*)d_in[i];
        else if (s == (long long)OUTC)            b2 = (const float*)d_in[i];
    }
    if (!x)  x  = (const float*)d_in[0];
    if (!ei) ei = d_in[1];
    if (!ew) ew = (const float*)d_in[2];
    if (!W1) W1 = (const float*)d_in[3];
    if (!b1) b1 = (const float*)d_in[4];
    if (!W2) W2 = (const float*)d_in[5];
    if (!b2) b2 = (const float*)d_in[6];
    float* out = (float*)d_out;

    void *pT1, *pT2, *pH, *pP0, *pP1h, *pP2h;
    cudaGetSymbolAddress(&pT1,  g_T1);
    cudaGetSymbolAddress(&pT2,  g_T2);
    cudaGetSymbolAddress(&pH,   g_H);
    cudaGetSymbolAddress(&pP0,  g_P0);
    cudaGetSymbolAddress(&pP1h, g_P1h);
    cudaGetSymbolAddress(&pP2h, g_P2h);

    int nb = (NN + 255) / 256;
    int eb = (EE + 255) / 256;

    detect_kernel<<<1, 32>>>((const long long*)ei);
    zero_kernel<<<nb, 256>>>();
    x2h_kernel<<<(NN * INC / 2 + 255) / 256, 256>>>(x);
    deg_count_kernel<<<eb, 256>>>(ei, ew);
    dinv_kernel<<<nb, 256>>>();
    scan_local_kernel<<<SCAN_BLOCKS, 256>>>();
    scan_blocks_kernel<<<1, 128>>>();
    scan_add_kernel<<<SCAN_BLOCKS, 256>>>();
    scatter_kernel<<<eb, 256>>>(ei, ew);
    transpose_w2_kernel<<<(3 * HIDC * OUTC + 255) / 256, 256>>>(W2);

    int sg = (NN * 32 + 255) / 256;  // warp per row

    // ---- layer 1 ----
    spmm1_kernel<<<sg, 256>>>();
    spmm2_kernel<<<sg, 256>>>(x);
    dim3 g1((NN + 127) / 128, HIDC / 64);
    gemm3_kernel<INC, HIDC, true><<<g1, 256>>>(
        x, (const float*)pT1, (const float*)pT2, W1, b1, (float*)pH);

    // ---- layer 2 (commuted; fp16 gathers) ----
    dim3 g2((NN + 127) / 128, 3);
    gemm1_kernel<<<g2, 256>>>((const float*)pH, (float*)pP0, (__half*)pP1h, (__half*)pP2h);
    spmm_dual_kernel<<<sg, 256>>>();
    spmm_final_kernel<<<sg, 256>>>(b2, out);
}

// round 8
// speedup vs baseline: 1.4152x; 1.1297x over previous
#include <cuda_runtime.h>
#include <cuda_fp16.h>
#include <cstdint>

#define NN 100000
#define EE 3200000
#define INC 128
#define HIDC 256
#define OUTC 64
#define KTOT1 (3 * INC)    // 384
#define NTOT2 (3 * OUTC)   // 192

static const int SCAN_CHUNK = 1024;
static const int SCAN_BLOCKS = (NN + SCAN_CHUNK - 1) / SCAN_CHUNK; // 98

// ---------------- scratch (static device arrays; no cudaMalloc) -------------
__device__ int   g_is64;
__device__ float g_deg[NN];
__device__ float g_dinv[NN];
__device__ int   g_count[NN];
__device__ int   g_rowstart[NN + 1];
__device__ int   g_cursor[NN];
__device__ int   g_blocksums[SCAN_BLOCKS];
__device__ int   g_csr_col[EE];
__device__ float g_csr_val[EE];

__device__ __align__(16) __half g_xh [(size_t)NN * INC];
__device__ __align__(16) __half g_xl [(size_t)NN * INC];
__device__ __align__(16) __half g_T1h[(size_t)NN * INC];
__device__ __align__(16) __half g_T1l[(size_t)NN * INC];
__device__ __align__(16) __half g_T2h[(size_t)NN * INC];
__device__ __align__(16) __half g_T2l[(size_t)NN * INC];
__device__ __align__(16) __half g_Hh [(size_t)NN * HIDC];
__device__ __align__(16) __half g_Hl [(size_t)NN * HIDC];
__device__ float g_P0 [(size_t)NN * OUTC];
__device__ __align__(16) __half g_P1h[(size_t)NN * OUTC];
__device__ __align__(16) __half g_P2h[(size_t)NN * OUTC];
__device__ float g_Q1 [(size_t)NN * OUTC];
__device__ __align__(16) __half g_Q2h[(size_t)NN * OUTC];
__device__ __align__(16) __half g_W1h[KTOT1 * HIDC];
__device__ __align__(16) __half g_W1l[KTOT1 * HIDC];
__device__ __align__(16) __half g_W2th[HIDC * NTOT2];
__device__ __align__(16) __half g_W2tl[HIDC * NTOT2];

// ---------------- edge-index dtype helpers ----------------------------------
__global__ void detect_kernel(const long long* __restrict__ ei) {
    if (threadIdx.x != 0 || blockIdx.x != 0) return;
    int is64 = 1;
    for (int i = 0; i < 4096; i++) {
        long long v = ei[i];
        if (v < 0 || v >= (long long)NN) { is64 = 0; break; }
    }
    g_is64 = is64;
}

__device__ __forceinline__ int clampN(long long v) {
    if (v < 0) return 0;
    if (v >= NN) return NN - 1;
    return (int)v;
}
__device__ __forceinline__ int edge_row(const void* ei, int e) {
    long long v = g_is64 ? ((const long long*)ei)[e] : (long long)((const int*)ei)[e];
    return clampN(v);
}
__device__ __forceinline__ int edge_col(const void* ei, int e) {
    long long v = g_is64 ? ((const long long*)ei)[(size_t)EE + e]
                         : (long long)((const int*)ei)[(size_t)EE + e];
    return clampN(v);
}

__device__ __forceinline__ void split_h(float v, __half& hi, __half& lo) {
    hi = __float2half_rn(v);
    lo = __float2half_rn(v - __half2float(hi));
}

// ---------------- prep kernels ----------------------------------------------
__global__ void zero_kernel() {
    int i = blockIdx.x * blockDim.x + threadIdx.x;
    if (i < NN) { g_deg[i] = 0.f; g_count[i] = 0; }
}

__global__ void x2h_kernel(const float* __restrict__ x) {
    int i = blockIdx.x * blockDim.x + threadIdx.x;
    const int total = NN * INC;
    if (i >= total) return;
    float v = x[i];
    __half hi, lo; split_h(v, hi, lo);
    g_xh[i] = hi;
    g_xl[i] = lo;
}

__global__ void w1split_kernel(const float* __restrict__ W1) {
    int i = blockIdx.x * blockDim.x + threadIdx.x;
    if (i >= KTOT1 * HIDC) return;
    __half hi, lo; split_h(W1[i], hi, lo);
    g_W1h[i] = hi;
    g_W1l[i] = lo;
}

// W2 [3][256][64] -> W2t [256][192] split into hi/lo
__global__ void w2tsplit_kernel(const float* __restrict__ W2) {
    int i = blockIdx.x * blockDim.x + threadIdx.x;
    if (i >= 3 * HIDC * OUTC) return;
    int k = i / (HIDC * OUTC);
    int rem = i - k * (HIDC * OUTC);
    int c = rem / OUTC;
    int j = rem - c * OUTC;
    __half hi, lo; split_h(W2[i], hi, lo);
    int o = c * NTOT2 + k * OUTC + j;
    g_W2th[o] = hi;
    g_W2tl[o] = lo;
}

__global__ void deg_count_kernel(const void* __restrict__ ei,
                                 const float* __restrict__ ew) {
    int e = blockIdx.x * blockDim.x + threadIdx.x;
    if (e >= EE) return;
    int r = edge_row(ei, e);
    atomicAdd(&g_deg[r], ew[e]);
    atomicAdd(&g_count[r], 1);
}

__global__ void dinv_kernel() {
    int i = blockIdx.x * blockDim.x + threadIdx.x;
    if (i >= NN) return;
    float d = g_deg[i];
    g_dinv[i] = (d > 0.f) ? rsqrtf(d) : 0.f;
}

__global__ void scan_local_kernel() {
    __shared__ int sd[256];
    int b = blockIdx.x, t = threadIdx.x;
    int base = b * SCAN_CHUNK + t * 4;
    int v0 = 0, v1 = 0, v2 = 0, v3 = 0;
    if (base + 0 < NN) v0 = g_count[base + 0];
    if (base + 1 < NN) v1 = g_count[base + 1];
    if (base + 2 < NN) v2 = g_count[base + 2];
    if (base + 3 < NN) v3 = g_count[base + 3];
    int s = v0 + v1 + v2 + v3;
    sd[t] = s;
    __syncthreads();
    for (int off = 1; off < 256; off <<= 1) {
        int tmp = (t >= off) ? sd[t - off] : 0;
        __syncthreads();
        sd[t] += tmp;
        __syncthreads();
    }
    int excl = sd[t] - s;
    if (base + 0 < NN) g_rowstart[base + 0] = excl;
    excl += v0;
    if (base + 1 < NN) g_rowstart[base + 1] = excl;
    excl += v1;
    if (base + 2 < NN) g_rowstart[base + 2] = excl;
    excl += v2;
    if (base + 3 < NN) g_rowstart[base + 3] = excl;
    if (t == 255) g_blocksums[b] = sd[255];
}

__global__ void scan_blocks_kernel() {
    __shared__ int sd[128];
    int t = threadIdx.x;
    int v = (t < SCAN_BLOCKS) ? g_blocksums[t] : 0;
    sd[t] = v;
    __syncthreads();
    for (int off = 1; off < 128; off <<= 1) {
        int tmp = (t >= off) ? sd[t - off] : 0;
        __syncthreads();
        sd[t] += tmp;
        __syncthreads();
    }
    if (t < SCAN_BLOCKS) g_blocksums[t] = sd[t] - v;  // exclusive
}

__global__ void scan_add_kernel() {
    int b = blockIdx.x, t = threadIdx.x;
    int off = g_blocksums[b];
    int base = b * SCAN_CHUNK + t * 4;
#pragma unroll
    for (int j = 0; j < 4; j++) {
        int idx = base + j;
        if (idx < NN) {
            int rv = g_rowstart[idx] + off;
            g_rowstart[idx] = rv;
            g_cursor[idx]   = rv;
        }
    }
    if (b == 0 && t == 0) g_rowstart[NN] = EE;
}

__global__ void scatter_kernel(const void* __restrict__ ei,
                               const float* __restrict__ ew) {
    int e = blockIdx.x * blockDim.x + threadIdx.x;
    if (e >= EE) return;
    int r = edge_row(ei, e);
    int c = edge_col(ei, e);
    float w = ew[e];
    float nv = -(g_dinv[r] * w * g_dinv[c]);
    int pos = atomicAdd(&g_cursor[r], 1);
    if (pos < 0) pos = 0;
    if (pos >= EE) pos = EE - 1;
    g_csr_col[pos] = c;
    g_csr_val[pos] = nv;
}

// ---------------- SpMM kernels (half gather, fp32 accumulate) ---------------
__device__ __forceinline__ void row_range(int w, int& s, int& e) {
    s = g_rowstart[w];
    e = g_rowstart[w + 1];
    if (s < 0) s = 0;
    if (e > EE) e = EE;
    if (e < s) e = s;
}

// T1 = L @ xh ; writes T1h/T1l (hi for next gather & GEMM, lo for GEMM)
__global__ void spmm1_kernel() {
    int w = (blockIdx.x * blockDim.x + threadIdx.x) >> 5;
    int lane = threadIdx.x & 31;
    if (w >= NN) return;
    int s, e; row_range(w, s, e);
    float4 a = make_float4(0.f, 0.f, 0.f, 0.f);
    const __half2* __restrict__ xh = reinterpret_cast<const __half2*>(g_xh);
    const int* __restrict__ cols = g_csr_col;
    const float* __restrict__ vals = g_csr_val;
    for (int base = s; base < e; base += 32) {
        int i = base + lane;
        int c = 0; float vv = 0.f;
        if (i < e) { c = cols[i]; vv = vals[i]; }
        int cnt = min(32, e - base);
        for (int j = 0; j < cnt; j++) {
            int   cc  = __shfl_sync(0xffffffffu, c, j);
            float val = __shfl_sync(0xffffffffu, vv, j);
            float2 f0 = __half22float2(xh[(size_t)cc * 64 + lane * 2]);
            float2 f1 = __half22float2(xh[(size_t)cc * 64 + lane * 2 + 1]);
            a.x = fmaf(val, f0.x, a.x);
            a.y = fmaf(val, f0.y, a.y);
            a.z = fmaf(val, f1.x, a.z);
            a.w = fmaf(val, f1.y, a.w);
        }
    }
    size_t o = (size_t)w * INC + lane * 4;
    __half h0, l0, h1, l1, h2, l2, h3, l3;
    split_h(a.x, h0, l0); split_h(a.y, h1, l1);
    split_h(a.z, h2, l2); split_h(a.w, h3, l3);
    *reinterpret_cast<__half2*>(&g_T1h[o])     = __halves2half2(h0, h1);
    *reinterpret_cast<__half2*>(&g_T1h[o + 2]) = __halves2half2(h2, h3);
    *reinterpret_cast<__half2*>(&g_T1l[o])     = __halves2half2(l0, l1);
    *reinterpret_cast<__half2*>(&g_T1l[o + 2]) = __halves2half2(l2, l3);
}

// T2 = 2 * (L @ T1h) - x   -> T2h/T2l
__global__ void spmm2_kernel(const float* __restrict__ x) {
    int w = (blockIdx.x * blockDim.x + threadIdx.x) >> 5;
    int lane = threadIdx.x & 31;
    if (w >= NN) return;
    int s, e; row_range(w, s, e);
    float4 a = make_float4(0.f, 0.f, 0.f, 0.f);
    const __half2* __restrict__ t1h = reinterpret_cast<const __half2*>(g_T1h);
    const int* __restrict__ cols = g_csr_col;
    const float* __restrict__ vals = g_csr_val;
    for (int base = s; base < e; base += 32) {
        int i = base + lane;
        int c = 0; float vv = 0.f;
        if (i < e) { c = cols[i]; vv = vals[i]; }
        int cnt = min(32, e - base);
        for (int j = 0; j < cnt; j++) {
            int   cc  = __shfl_sync(0xffffffffu, c, j);
            float val = __shfl_sync(0xffffffffu, vv, j);
            float2 f0 = __half22float2(t1h[(size_t)cc * 64 + lane * 2]);
            float2 f1 = __half22float2(t1h[(size_t)cc * 64 + lane * 2 + 1]);
            a.x = fmaf(val, f0.x, a.x);
            a.y = fmaf(val, f0.y, a.y);
            a.z = fmaf(val, f1.x, a.z);
            a.w = fmaf(val, f1.y, a.w);
        }
    }
    float4 xs = reinterpret_cast<const float4*>(x)[(size_t)w * 32 + lane];
    float r0 = 2.f * a.x - xs.x;
    float r1 = 2.f * a.y - xs.y;
    float r2 = 2.f * a.z - xs.z;
    float r3 = 2.f * a.w - xs.w;
    size_t o = (size_t)w * INC + lane * 4;
    __half h0, l0, h1, l1, h2, l2, h3, l3;
    split_h(r0, h0, l0); split_h(r1, h1, l1);
    split_h(r2, h2, l2); split_h(r3, h3, l3);
    *reinterpret_cast<__half2*>(&g_T2h[o])     = __halves2half2(h0, h1);
    *reinterpret_cast<__half2*>(&g_T2h[o + 2]) = __halves2half2(h2, h3);
    *reinterpret_cast<__half2*>(&g_T2l[o])     = __halves2half2(l0, l1);
    *reinterpret_cast<__half2*>(&g_T2l[o + 2]) = __halves2half2(l2, l3);
}

// Q1 = L @ P1h (fp32 out), Q2h = half(L @ P2h)
__global__ void spmm_dual_kernel() {
    int w = (blockIdx.x * blockDim.x + threadIdx.x) >> 5;
    int lane = threadIdx.x & 31;
    if (w >= NN) return;
    int s, e; row_range(w, s, e);
    float2 a1 = make_float2(0.f, 0.f);
    float2 a2 = make_float2(0.f, 0.f);
    const __half2* __restrict__ p1 = reinterpret_cast<const __half2*>(g_P1h);
    const __half2* __restrict__ p2 = reinterpret_cast<const __half2*>(g_P2h);
    const int* __restrict__ cols = g_csr_col;
    const float* __restrict__ vals = g_csr_val;
    for (int base = s; base < e; base += 32) {
        int i = base + lane;
        int c = 0; float vv = 0.f;
        if (i < e) { c = cols[i]; vv = vals[i]; }
        int cnt = min(32, e - base);
        for (int j = 0; j < cnt; j++) {
            int   cc  = __shfl_sync(0xffffffffu, c, j);
            float val = __shfl_sync(0xffffffffu, vv, j);
            float2 f1 = __half22float2(p1[(size_t)cc * 32 + lane]);
            float2 f2 = __half22float2(p2[(size_t)cc * 32 + lane]);
            a1.x = fmaf(val, f1.x, a1.x);
            a1.y = fmaf(val, f1.y, a1.y);
            a2.x = fmaf(val, f2.x, a2.x);
            a2.y = fmaf(val, f2.y, a2.y);
        }
    }
    reinterpret_cast<float2*>(g_Q1)[(size_t)w * 32 + lane] = a1;
    reinterpret_cast<__half2*>(g_Q2h)[(size_t)w * 32 + lane] = __floats2half2_rn(a2.x, a2.y);
}

// out = 2 * (L @ Q2h) + P0 + Q1 - P2h + b2
__global__ void spmm_final_kernel(const float* __restrict__ b2,
                                  float* __restrict__ out) {
    int w = (blockIdx.x * blockDim.x + threadIdx.x) >> 5;
    int lane = threadIdx.x & 31;
    if (w >= NN) return;
    int s, e; row_range(w, s, e);
    float2 a = make_float2(0.f, 0.f);
    const __half2* __restrict__ q2 = reinterpret_cast<const __half2*>(g_Q2h);
    const int* __restrict__ cols = g_csr_col;
    const float* __restrict__ vals = g_csr_val;
    for (int base = s; base < e; base += 32) {
        int i = base + lane;
        int c = 0; float vv = 0.f;
        if (i < e) { c = cols[i]; vv = vals[i]; }
        int cnt = min(32, e - base);
        for (int j = 0; j < cnt; j++) {
            int   cc  = __shfl_sync(0xffffffffu, c, j);
            float val = __shfl_sync(0xffffffffu, vv, j);
            float2 f = __half22float2(q2[(size_t)cc * 32 + lane]);
            a.x = fmaf(val, f.x, a.x);
            a.y = fmaf(val, f.y, a.y);
        }
    }
    float2 p0 = reinterpret_cast<const float2*>(g_P0)[(size_t)w * 32 + lane];
    float2 q1 = reinterpret_cast<const float2*>(g_Q1)[(size_t)w * 32 + lane];
    float2 p2 = __half22float2(reinterpret_cast<const __half2*>(g_P2h)[(size_t)w * 32 + lane]);
    float2 bb = reinterpret_cast<const float2*>(b2)[lane];
    float2 r;
    r.x = 2.f * a.x + p0.x + q1.x - p2.x + bb.x;
    r.y = 2.f * a.y + p0.y + q1.y - p2.y + bb.y;
    reinterpret_cast<float2*>(out)[(size_t)w * 32 + lane] = r;
}

// ---------------- split-fp16 tensor-core GEMM machinery ---------------------
#define MMA16816(d, a, b)                                                     \
    asm volatile(                                                             \
        "mma.sync.aligned.m16n8k16.row.col.f32.f16.f16.f32 "                  \
        "{%0,%1,%2,%3}, {%4,%5,%6,%7}, {%8,%9}, {%0,%1,%2,%3};"               \
        : "+f"((d)[0]), "+f"((d)[1]), "+f"((d)[2]), "+f"((d)[3])              \
        : "r"((a)[0]), "r"((a)[1]), "r"((a)[2]), "r"((a)[3]),                 \
          "r"((b)[0]), "r"((b)[1]))

#define AS_STRIDE 24   // halves per row (16 + 8 pad) -> conflict-free frag lds
#define WS_STRIDE 24

// ---- layer 1: H(hi/lo) = relu([x|T1|T2] @ W1 + b1), M=NN, N=256, K=384 ----
__global__ __launch_bounds__(256) void gemm_l1_kernel(const float* __restrict__ bias) {
    __shared__ __half Ash[128 * AS_STRIDE];
    __shared__ __half Asl[128 * AS_STRIDE];
    __shared__ __half Wsh[64 * WS_STRIDE];
    __shared__ __half Wsl[64 * WS_STRIDE];

    int tid = threadIdx.x;
    int m0 = blockIdx.x * 128;
    int n0 = blockIdx.y * 64;
    int lane = tid & 31, wid = tid >> 5;
    int wm = (wid & 3) * 32;
    int wn = (wid >> 2) * 32;
    int g = lane >> 2, c = lane & 3;

    float acc[2][4][4];
#pragma unroll
    for (int i = 0; i < 2; i++)
#pragma unroll
        for (int j = 0; j < 4; j++)
#pragma unroll
            for (int k = 0; k < 4; k++) acc[i][j][k] = 0.f;

    // staging indices
    int ar = tid >> 1, ah8 = (tid & 1) * 8;      // A: 2 thr/row, 8 halves each
    int wk = tid >> 4, wn4 = (tid & 15) * 4;     // W: 16 thr/k-row, 4 cols each

    for (int k0 = 0; k0 < KTOT1; k0 += 16) {
        int src = k0 >> 7;            // 0,1,2
        int kc  = k0 & 127;
        const __half* Ah = (src == 0) ? g_xh : ((src == 1) ? g_T1h : g_T2h);
        const __half* Al = (src == 0) ? g_xl : ((src == 1) ? g_T1l : g_T2l);

        // stage A (128 x 16, hi+lo)
        {
            int gm = m0 + ar;
            uint4 vh = make_uint4(0u, 0u, 0u, 0u), vl = vh;
            if (gm < NN) {
                size_t off = (size_t)gm * INC + kc + ah8;
                vh = *reinterpret_cast<const uint4*>(Ah + off);
                vl = *reinterpret_cast<const uint4*>(Al + off);
            }
            *reinterpret_cast<uint4*>(&Ash[ar * AS_STRIDE + ah8]) = vh;
            *reinterpret_cast<uint4*>(&Asl[ar * AS_STRIDE + ah8]) = vl;
        }
        // stage W transposed (16 x 64 -> [n][k])
        {
            size_t off = (size_t)(k0 + wk) * HIDC + n0 + wn4;
            __half2 h01 = *reinterpret_cast<const __half2*>(g_W1h + off);
            __half2 h23 = *reinterpret_cast<const __half2*>(g_W1h + off + 2);
            __half2 l01 = *reinterpret_cast<const __half2*>(g_W1l + off);
            __half2 l23 = *reinterpret_cast<const __half2*>(g_W1l + off + 2);
            Wsh[(wn4 + 0) * WS_STRIDE + wk] = __low2half(h01);
            Wsh[(wn4 + 1) * WS_STRIDE + wk] = __high2half(h01);
            Wsh[(wn4 + 2) * WS_STRIDE + wk] = __low2half(h23);
            Wsh[(wn4 + 3) * WS_STRIDE + wk] = __high2half(h23);
            Wsl[(wn4 + 0) * WS_STRIDE + wk] = __low2half(l01);
            Wsl[(wn4 + 1) * WS_STRIDE + wk] = __high2half(l01);
            Wsl[(wn4 + 2) * WS_STRIDE + wk] = __low2half(l23);
            Wsl[(wn4 + 3) * WS_STRIDE + wk] = __high2half(l23);
        }
        __syncthreads();

        uint32_t afh[2][4], afl[2][4], bfh[4][2], bfl[4][2];
#pragma unroll
        for (int i = 0; i < 2; i++) {
            int rb = wm + i * 16 + g;
            afh[i][0] = *reinterpret_cast<const uint32_t*>(&Ash[rb * AS_STRIDE + 2 * c]);
            afh[i][1] = *reinterpret_cast<const uint32_t*>(&Ash[(rb + 8) * AS_STRIDE + 2 * c]);
            afh[i][2] = *reinterpret_cast<const uint32_t*>(&Ash[rb * AS_STRIDE + 2 * c + 8]);
            afh[i][3] = *reinterpret_cast<const uint32_t*>(&Ash[(rb + 8) * AS_STRIDE + 2 * c + 8]);
            afl[i][0] = *reinterpret_cast<const uint32_t*>(&Asl[rb * AS_STRIDE + 2 * c]);
            afl[i][1] = *reinterpret_cast<const uint32_t*>(&Asl[(rb + 8) * AS_STRIDE + 2 * c]);
            afl[i][2] = *reinterpret_cast<const uint32_t*>(&Asl[rb * AS_STRIDE + 2 * c + 8]);
            afl[i][3] = *reinterpret_cast<const uint32_t*>(&Asl[(rb + 8) * AS_STRIDE + 2 * c + 8]);
        }
#pragma unroll
        for (int j = 0; j < 4; j++) {
            int nb = wn + j * 8 + g;
            bfh[j][0] = *reinterpret_cast<const uint32_t*>(&Wsh[nb * WS_STRIDE + 2 * c]);
            bfh[j][1] = *reinterpret_cast<const uint32_t*>(&Wsh[nb * WS_STRIDE + 2 * c + 8]);
            bfl[j][0] = *reinterpret_cast<const uint32_t*>(&Wsl[nb * WS_STRIDE + 2 * c]);
            bfl[j][1] = *reinterpret_cast<const uint32_t*>(&Wsl[nb * WS_STRIDE + 2 * c + 8]);
        }
#pragma unroll
        for (int i = 0; i < 2; i++)
#pragma unroll
            for (int j = 0; j < 4; j++) {
                MMA16816(acc[i][j], afh[i], bfh[j]);
                MMA16816(acc[i][j], afh[i], bfl[j]);
                MMA16816(acc[i][j], afl[i], bfh[j]);
            }
        __syncthreads();
    }

    // epilogue: bias + relu -> Hh/Hl
#pragma unroll
    for (int i = 0; i < 2; i++) {
#pragma unroll
        for (int j = 0; j < 4; j++) {
            int col = n0 + wn + j * 8 + 2 * c;
            float b0 = bias[col], b1v = bias[col + 1];
            int r0 = m0 + wm + i * 16 + g;
            int r1 = r0 + 8;
            float v0 = fmaxf(acc[i][j][0] + b0, 0.f);
            float v1 = fmaxf(acc[i][j][1] + b1v, 0.f);
            float v2 = fmaxf(acc[i][j][2] + b0, 0.f);
            float v3 = fmaxf(acc[i][j][3] + b1v, 0.f);
            if (r0 < NN) {
                __half h0, l0, h1, l1;
                split_h(v0, h0, l0); split_h(v1, h1, l1);
                size_t o = (size_t)r0 * HIDC + col;
                *reinterpret_cast<__half2*>(&g_Hh[o]) = __halves2half2(h0, h1);
                *reinterpret_cast<__half2*>(&g_Hl[o]) = __halves2half2(l0, l1);
            }
            if (r1 < NN) {
                __half h2, l2, h3, l3;
                split_h(v2, h2, l2); split_h(v3, h3, l3);
                size_t o = (size_t)r1 * HIDC + col;
                *reinterpret_cast<__half2*>(&g_Hh[o]) = __halves2half2(h2, h3);
                *reinterpret_cast<__half2*>(&g_Hl[o]) = __halves2half2(l2, l3);
            }
        }
    }
}

// ---- layer 2: P_y = H @ W2t[:, 64y:...], M=NN, N=192, K=256 ----------------
__global__ __launch_bounds__(256) void gemm_l2_kernel() {
    __shared__ __half Ash[128 * AS_STRIDE];
    __shared__ __half Asl[128 * AS_STRIDE];
    __shared__ __half Wsh[64 * WS_STRIDE];
    __shared__ __half Wsl[64 * WS_STRIDE];

    int tid = threadIdx.x;
    int m0 = blockIdx.x * 128;
    int y  = blockIdx.y;
    int n0 = y * 64;
    int lane = tid & 31, wid = tid >> 5;
    int wm = (wid & 3) * 32;
    int wn = (wid >> 2) * 32;
    int g = lane >> 2, c = lane & 3;

    float acc[2][4][4];
#pragma unroll
    for (int i = 0; i < 2; i++)
#pragma unroll
        for (int j = 0; j < 4; j++)
#pragma unroll
            for (int k = 0; k < 4; k++) acc[i][j][k] = 0.f;

    int ar = tid >> 1, ah8 = (tid & 1) * 8;
    int wk = tid >> 4, wn4 = (tid & 15) * 4;

    for (int k0 = 0; k0 < HIDC; k0 += 16) {
        {
            int gm = m0 + ar;
            uint4 vh = make_uint4(0u, 0u, 0u, 0u), vl = vh;
            if (gm < NN) {
                size_t off = (size_t)gm * HIDC + k0 + ah8;
                vh = *reinterpret_cast<const uint4*>(g_Hh + off);
                vl = *reinterpret_cast<const uint4*>(g_Hl + off);
            }
            *reinterpret_cast<uint4*>(&Ash[ar * AS_STRIDE + ah8]) = vh;
            *reinterpret_cast<uint4*>(&Asl[ar * AS_STRIDE + ah8]) = vl;
        }
        {
            size_t off = (size_t)(k0 + wk) * NTOT2 + n0 + wn4;
            __half2 h01 = *reinterpret_cast<const __half2*>(g_W2th + off);
            __half2 h23 = *reinterpret_cast<const __half2*>(g_W2th + off + 2);
            __half2 l01 = *reinterpret_cast<const __half2*>(g_W2tl + off);
            __half2 l23 = *reinterpret_cast<const __half2*>(g_W2tl + off + 2);
            Wsh[(wn4 + 0) * WS_STRIDE + wk] = __low2half(h01);
            Wsh[(wn4 + 1) * WS_STRIDE + wk] = __high2half(h01);
            Wsh[(wn4 + 2) * WS_STRIDE + wk] = __low2half(h23);
            Wsh[(wn4 + 3) * WS_STRIDE + wk] = __high2half(h23);
            Wsl[(wn4 + 0) * WS_STRIDE + wk] = __low2half(l01);
            Wsl[(wn4 + 1) * WS_STRIDE + wk] = __high2half(l01);
            Wsl[(wn4 + 2) * WS_STRIDE + wk] = __low2half(l23);
            Wsl[(wn4 + 3) * WS_STRIDE + wk] = __high2half(l23);
        }
        __syncthreads();

        uint32_t afh[2][4], afl[2][4], bfh[4][2], bfl[4][2];
#pragma unroll
        for (int i = 0; i < 2; i++) {
            int rb = wm + i * 16 + g;
            afh[i][0] = *reinterpret_cast<const uint32_t*>(&Ash[rb * AS_STRIDE + 2 * c]);
            afh[i][1] = *reinterpret_cast<const uint32_t*>(&Ash[(rb + 8) * AS_STRIDE + 2 * c]);
            afh[i][2] = *reinterpret_cast<const uint32_t*>(&Ash[rb * AS_STRIDE + 2 * c + 8]);
            afh[i][3] = *reinterpret_cast<const uint32_t*>(&Ash[(rb + 8) * AS_STRIDE + 2 * c + 8]);
            afl[i][0] = *reinterpret_cast<const uint32_t*>(&Asl[rb * AS_STRIDE + 2 * c]);
            afl[i][1] = *reinterpret_cast<const uint32_t*>(&Asl[(rb + 8) * AS_STRIDE + 2 * c]);
            afl[i][2] = *reinterpret_cast<const uint32_t*>(&Asl[rb * AS_STRIDE + 2 * c + 8]);
            afl[i][3] = *reinterpret_cast<const uint32_t*>(&Asl[(rb + 8) * AS_STRIDE + 2 * c + 8]);
        }
#pragma unroll
        for (int j = 0; j < 4; j++) {
            int nb = wn + j * 8 + g;
            bfh[j][0] = *reinterpret_cast<const uint32_t*>(&Wsh[nb * WS_STRIDE + 2 * c]);
            bfh[j][1] = *reinterpret_cast<const uint32_t*>(&Wsh[nb * WS_STRIDE + 2 * c + 8]);
            bfl[j][0] = *reinterpret_cast<const uint32_t*>(&Wsl[nb * WS_STRIDE + 2 * c]);
            bfl[j][1] = *reinterpret_cast<const uint32_t*>(&Wsl[nb * WS_STRIDE + 2 * c + 8]);
        }
#pragma unroll
        for (int i = 0; i < 2; i++)
#pragma unroll
            for (int j = 0; j < 4; j++) {
                MMA16816(acc[i][j], afh[i], bfh[j]);
                MMA16816(acc[i][j], afh[i], bfl[j]);
                MMA16816(acc[i][j], afl[i], bfh[j]);
            }
        __syncthreads();
    }

    // epilogue by y: 0 -> P0 fp32, 1 -> P1h, 2 -> P2h (cols are local 0..63)
#pragma unroll
    for (int i = 0; i < 2; i++) {
#pragma unroll
        for (int j = 0; j < 4; j++) {
            int col = wn + j * 8 + 2 * c;
            int r0 = m0 + wm + i * 16 + g;
            int r1 = r0 + 8;
            if (r0 < NN) {
                size_t o = (size_t)r0 * OUTC + col;
                if (y == 0)
                    *reinterpret_cast<float2*>(&g_P0[o]) = make_float2(acc[i][j][0], acc[i][j][1]);
                else if (y == 1)
                    *reinterpret_cast<__half2*>(&g_P1h[o]) = __floats2half2_rn(acc[i][j][0], acc[i][j][1]);
                else
                    *reinterpret_cast<__half2*>(&g_P2h[o]) = __floats2half2_rn(acc[i][j][0], acc[i][j][1]);
            }
            if (r1 < NN) {
                size_t o = (size_t)r1 * OUTC + col;
                if (y == 0)
                    *reinterpret_cast<float2*>(&g_P0[o]) = make_float2(acc[i][j][2], acc[i][j][3]);
                else if (y == 1)
                    *reinterpret_cast<__half2*>(&g_P1h[o]) = __floats2half2_rn(acc[i][j][2], acc[i][j][3]);
                else
                    *reinterpret_cast<__half2*>(&g_P2h[o]) = __floats2half2_rn(acc[i][j][2], acc[i][j][3]);
            }
        }
    }
}

// ---------------- launch ----------------------------------------------------
extern "C" void kernel_launch(void* const* d_in, const int* in_sizes, int n_in,
                              void* d_out, int out_size) {
    const float* x  = nullptr; const void* ei = nullptr; const float* ew = nullptr;
    const float* W1 = nullptr; const float* b1 = nullptr;
    const float* W2 = nullptr; const float* b2 = nullptr;
    for (int i = 0; i < n_in; i++) {
        long long s = in_sizes[i];
        if      (s == (long long)NN * INC)        x  = (const float*)d_in[i];
        else if (s == 2LL * EE)                   ei = d_in[i];
        else if (s == (long long)EE)              ew = (const float*)d_in[i];
        else if (s == 3LL * INC * HIDC)           W1 = (const float*)d_in[i];
        else if (s == (long long)HIDC)            b1 = (const float*)d_in[i];
        else if (s == 3LL * HIDC * OUTC)          W2 = (const float*)d_in[i];
        else if (s == (long long)OUTC)            b2 = (const float*)d_in[i];
    }
    if (!x)  x  = (const float*)d_in[0];
    if (!ei) ei = d_in[1];
    if (!ew) ew = (const float*)d_in[2];
    if (!W1) W1 = (const float*)d_in[3];
    if (!b1) b1 = (const float*)d_in[4];
    if (!W2) W2 = (const float*)d_in[5];
    if (!b2) b2 = (const float*)d_in[6];
    float* out = (float*)d_out;

    int nb = (NN + 255) / 256;
    int eb = (EE + 255) / 256;

    detect_kernel<<<1, 32>>>((const long long*)ei);
    zero_kernel<<<nb, 256>>>();
    x2h_kernel<<<(NN * INC + 255) / 256, 256>>>(x);
    w1split_kernel<<<(KTOT1 * HIDC + 255) / 256, 256>>>(W1);
    w2tsplit_kernel<<<(3 * HIDC * OUTC + 255) / 256, 256>>>(W2);
    deg_count_kernel<<<eb, 256>>>(ei, ew);
    dinv_kernel<<<nb, 256>>>();
    scan_local_kernel<<<SCAN_BLOCKS, 256>>>();
    scan_blocks_kernel<<<1, 128>>>();
    scan_add_kernel<<<SCAN_BLOCKS, 256>>>();
    scatter_kernel<<<eb, 256>>>(ei, ew);

    int sg = (NN * 32 + 255) / 256;  // warp per row

    // ---- layer 1 ----
    spmm1_kernel<<<sg, 256>>>();
    spmm2_kernel<<<sg, 256>>>(x);
    dim3 g1((NN + 127) / 128, HIDC / 64);
    gemm_l1_kernel<<<g1, 256>>>(b1);

    // ---- layer 2 (commuted; fp16 gathers) ----
    dim3 g2((NN + 127) / 128, 3);
    gemm_l2_kernel<<<g2, 256>>>();
    spmm_dual_kernel<<<sg, 256>>>();
    spmm_final_kernel<<<sg, 256>>>(b2, out);
}

// round 9
// speedup vs baseline: 1.7731x; 1.2530x over previous
#include <cuda_runtime.h>
#include <cuda_fp16.h>
#include <cstdint>

#define NN 100000
#define EE 3200000
#define INC 128
#define HIDC 256
#define OUTC 64
#define KTOT1 (3 * INC)    // 384
#define NTOT2 (3 * OUTC)   // 192

static const int SCAN_CHUNK = 1024;
static const int SCAN_BLOCKS = (NN + SCAN_CHUNK - 1) / SCAN_CHUNK; // 98

// ---------------- scratch (static device arrays; no cudaMalloc) -------------
__device__ int   g_is64;
__device__ float g_deg[NN];
__device__ float g_dinv[NN];
__device__ int   g_count[NN];
__device__ int   g_rowstart[NN + 1];
__device__ int   g_cursor[NN];
__device__ int   g_blocksums[SCAN_BLOCKS];
__device__ int   g_csr_col[EE];
__device__ float g_csr_val[EE];

__device__ __align__(16) __half g_xh [(size_t)NN * INC];
__device__ __align__(16) __half g_xl [(size_t)NN * INC];
__device__ __align__(16) __half g_T1h[(size_t)NN * INC];
__device__ __align__(16) __half g_T1l[(size_t)NN * INC];
__device__ __align__(16) __half g_T2h[(size_t)NN * INC];
__device__ __align__(16) __half g_T2l[(size_t)NN * INC];
__device__ __align__(16) __half g_Hh [(size_t)NN * HIDC];
__device__ __align__(16) __half g_Hl [(size_t)NN * HIDC];
__device__ float g_P0 [(size_t)NN * OUTC];
__device__ __align__(16) __half g_P1h[(size_t)NN * OUTC];
__device__ __align__(16) __half g_P2h[(size_t)NN * OUTC];
__device__ float g_Q1 [(size_t)NN * OUTC];
__device__ __align__(16) __half g_Q2h[(size_t)NN * OUTC];
__device__ __align__(16) __half g_W1h[KTOT1 * HIDC];
__device__ __align__(16) __half g_W2th[HIDC * NTOT2];

// ---------------- edge-index dtype helpers ----------------------------------
__global__ void detect_kernel(const long long* __restrict__ ei) {
    if (threadIdx.x != 0 || blockIdx.x != 0) return;
    int is64 = 1;
    for (int i = 0; i < 4096; i++) {
        long long v = ei[i];
        if (v < 0 || v >= (long long)NN) { is64 = 0; break; }
    }
    g_is64 = is64;
}

__device__ __forceinline__ int clampN(long long v) {
    if (v < 0) return 0;
    if (v >= NN) return NN - 1;
    return (int)v;
}
__device__ __forceinline__ int edge_row(const void* ei, int e) {
    long long v = g_is64 ? ((const long long*)ei)[e] : (long long)((const int*)ei)[e];
    return clampN(v);
}
__device__ __forceinline__ int edge_col(const void* ei, int e) {
    long long v = g_is64 ? ((const long long*)ei)[(size_t)EE + e]
                         : (long long)((const int*)ei)[(size_t)EE + e];
    return clampN(v);
}

__device__ __forceinline__ void split_h(float v, __half& hi, __half& lo) {
    hi = __float2half_rn(v);
    lo = __float2half_rn(v - __half2float(hi));
}

// ---------------- prep kernels ----------------------------------------------
__global__ void zero_kernel() {
    int i = blockIdx.x * blockDim.x + threadIdx.x;
    if (i < NN) { g_deg[i] = 0.f; g_count[i] = 0; }
}

__global__ void x2h_kernel(const float* __restrict__ x) {
    int i = blockIdx.x * blockDim.x + threadIdx.x;
    const int total = NN * INC;
    if (i >= total) return;
    float v = x[i];
    __half hi, lo; split_h(v, hi, lo);
    g_xh[i] = hi;
    g_xl[i] = lo;
}

__global__ void w1h_kernel(const float* __restrict__ W1) {
    int i = blockIdx.x * blockDim.x + threadIdx.x;
    if (i >= KTOT1 * HIDC) return;
    g_W1h[i] = __float2half_rn(W1[i]);
}

// W2 [3][256][64] -> W2t [256][192] (hi only)
__global__ void w2th_kernel(const float* __restrict__ W2) {
    int i = blockIdx.x * blockDim.x + threadIdx.x;
    if (i >= 3 * HIDC * OUTC) return;
    int k = i / (HIDC * OUTC);
    int rem = i - k * (HIDC * OUTC);
    int c = rem / OUTC;
    int j = rem - c * OUTC;
    g_W2th[c * NTOT2 + k * OUTC + j] = __float2half_rn(W2[i]);
}

__global__ void deg_count_kernel(const void* __restrict__ ei,
                                 const float* __restrict__ ew) {
    int e = blockIdx.x * blockDim.x + threadIdx.x;
    if (e >= EE) return;
    int r = edge_row(ei, e);
    atomicAdd(&g_deg[r], ew[e]);
    atomicAdd(&g_count[r], 1);
}

__global__ void dinv_kernel() {
    int i = blockIdx.x * blockDim.x + threadIdx.x;
    if (i >= NN) return;
    float d = g_deg[i];
    g_dinv[i] = (d > 0.f) ? rsqrtf(d) : 0.f;
}

__global__ void scan_local_kernel() {
    __shared__ int sd[256];
    int b = blockIdx.x, t = threadIdx.x;
    int base = b * SCAN_CHUNK + t * 4;
    int v0 = 0, v1 = 0, v2 = 0, v3 = 0;
    if (base + 0 < NN) v0 = g_count[base + 0];
    if (base + 1 < NN) v1 = g_count[base + 1];
    if (base + 2 < NN) v2 = g_count[base + 2];
    if (base + 3 < NN) v3 = g_count[base + 3];
    int s = v0 + v1 + v2 + v3;
    sd[t] = s;
    __syncthreads();
    for (int off = 1; off < 256; off <<= 1) {
        int tmp = (t >= off) ? sd[t - off] : 0;
        __syncthreads();
        sd[t] += tmp;
        __syncthreads();
    }
    int excl = sd[t] - s;
    if (base + 0 < NN) g_rowstart[base + 0] = excl;
    excl += v0;
    if (base + 1 < NN) g_rowstart[base + 1] = excl;
    excl += v1;
    if (base + 2 < NN) g_rowstart[base + 2] = excl;
    excl += v2;
    if (base + 3 < NN) g_rowstart[base + 3] = excl;
    if (t == 255) g_blocksums[b] = sd[255];
}

__global__ void scan_blocks_kernel() {
    __shared__ int sd[128];
    int t = threadIdx.x;
    int v = (t < SCAN_BLOCKS) ? g_blocksums[t] : 0;
    sd[t] = v;
    __syncthreads();
    for (int off = 1; off < 128; off <<= 1) {
        int tmp = (t >= off) ? sd[t - off] : 0;
        __syncthreads();
        sd[t] += tmp;
        __syncthreads();
    }
    if (t < SCAN_BLOCKS) g_blocksums[t] = sd[t] - v;  // exclusive
}

__global__ void scan_add_kernel() {
    int b = blockIdx.x, t = threadIdx.x;
    int off = g_blocksums[b];
    int base = b * SCAN_CHUNK + t * 4;
#pragma unroll
    for (int j = 0; j < 4; j++) {
        int idx = base + j;
        if (idx < NN) {
            int rv = g_rowstart[idx] + off;
            g_rowstart[idx] = rv;
            g_cursor[idx]   = rv;
        }
    }
    if (b == 0 && t == 0) g_rowstart[NN] = EE;
}

__global__ void scatter_kernel(const void* __restrict__ ei,
                               const float* __restrict__ ew) {
    int e = blockIdx.x * blockDim.x + threadIdx.x;
    if (e >= EE) return;
    int r = edge_row(ei, e);
    int c = edge_col(ei, e);
    float w = ew[e];
    float nv = -(g_dinv[r] * w * g_dinv[c]);
    int pos = atomicAdd(&g_cursor[r], 1);
    if (pos < 0) pos = 0;
    if (pos >= EE) pos = EE - 1;
    g_csr_col[pos] = c;
    g_csr_val[pos] = nv;
}

// ---------------- SpMM kernels (half gather, fp32 accumulate) ---------------
__device__ __forceinline__ void row_range(int w, int& s, int& e) {
    s = g_rowstart[w];
    e = g_rowstart[w + 1];
    if (s < 0) s = 0;
    if (e > EE) e = EE;
    if (e < s) e = s;
}

// T1 = L @ xh ; writes T1h/T1l
__global__ void spmm1_kernel() {
    int w = (blockIdx.x * blockDim.x + threadIdx.x) >> 5;
    int lane = threadIdx.x & 31;
    if (w >= NN) return;
    int s, e; row_range(w, s, e);
    float4 a = make_float4(0.f, 0.f, 0.f, 0.f);
    const __half2* __restrict__ xh = reinterpret_cast<const __half2*>(g_xh);
    const int* __restrict__ cols = g_csr_col;
    const float* __restrict__ vals = g_csr_val;
    for (int base = s; base < e; base += 32) {
        int i = base + lane;
        int c = 0; float vv = 0.f;
        if (i < e) { c = cols[i]; vv = vals[i]; }
        int cnt = min(32, e - base);
        for (int j = 0; j < cnt; j++) {
            int   cc  = __shfl_sync(0xffffffffu, c, j);
            float val = __shfl_sync(0xffffffffu, vv, j);
            float2 f0 = __half22float2(xh[(size_t)cc * 64 + lane * 2]);
            float2 f1 = __half22float2(xh[(size_t)cc * 64 + lane * 2 + 1]);
            a.x = fmaf(val, f0.x, a.x);
            a.y = fmaf(val, f0.y, a.y);
            a.z = fmaf(val, f1.x, a.z);
            a.w = fmaf(val, f1.y, a.w);
        }
    }
    size_t o = (size_t)w * INC + lane * 4;
    __half h0, l0, h1, l1, h2, l2, h3, l3;
    split_h(a.x, h0, l0); split_h(a.y, h1, l1);
    split_h(a.z, h2, l2); split_h(a.w, h3, l3);
    *reinterpret_cast<__half2*>(&g_T1h[o])     = __halves2half2(h0, h1);
    *reinterpret_cast<__half2*>(&g_T1h[o + 2]) = __halves2half2(h2, h3);
    *reinterpret_cast<__half2*>(&g_T1l[o])     = __halves2half2(l0, l1);
    *reinterpret_cast<__half2*>(&g_T1l[o + 2]) = __halves2half2(l2, l3);
}

// T2 = 2 * (L @ T1h) - x
__global__ void spmm2_kernel(const float* __restrict__ x) {
    int w = (blockIdx.x * blockDim.x + threadIdx.x) >> 5;
    int lane = threadIdx.x & 31;
    if (w >= NN) return;
    int s, e; row_range(w, s, e);
    float4 a = make_float4(0.f, 0.f, 0.f, 0.f);
    const __half2* __restrict__ t1h = reinterpret_cast<const __half2*>(g_T1h);
    const int* __restrict__ cols = g_csr_col;
    const float* __restrict__ vals = g_csr_val;
    for (int base = s; base < e; base += 32) {
        int i = base + lane;
        int c = 0; float vv = 0.f;
        if (i < e) { c = cols[i]; vv = vals[i]; }
        int cnt = min(32, e - base);
        for (int j = 0; j < cnt; j++) {
            int   cc  = __shfl_sync(0xffffffffu, c, j);
            float val = __shfl_sync(0xffffffffu, vv, j);
            float2 f0 = __half22float2(t1h[(size_t)cc * 64 + lane * 2]);
            float2 f1 = __half22float2(t1h[(size_t)cc * 64 + lane * 2 + 1]);
            a.x = fmaf(val, f0.x, a.x);
            a.y = fmaf(val, f0.y, a.y);
            a.z = fmaf(val, f1.x, a.z);
            a.w = fmaf(val, f1.y, a.w);
        }
    }
    float4 xs = reinterpret_cast<const float4*>(x)[(size_t)w * 32 + lane];
    float r0 = 2.f * a.x - xs.x;
    float r1 = 2.f * a.y - xs.y;
    float r2 = 2.f * a.z - xs.z;
    float r3 = 2.f * a.w - xs.w;
    size_t o = (size_t)w * INC + lane * 4;
    __half h0, l0, h1, l1, h2, l2, h3, l3;
    split_h(r0, h0, l0); split_h(r1, h1, l1);
    split_h(r2, h2, l2); split_h(r3, h3, l3);
    *reinterpret_cast<__half2*>(&g_T2h[o])     = __halves2half2(h0, h1);
    *reinterpret_cast<__half2*>(&g_T2h[o + 2]) = __halves2half2(h2, h3);
    *reinterpret_cast<__half2*>(&g_T2l[o])     = __halves2half2(l0, l1);
    *reinterpret_cast<__half2*>(&g_T2l[o + 2]) = __halves2half2(l2, l3);
}

// Q1 = L @ P1h (fp32 out), Q2h = half(L @ P2h)
__global__ void spmm_dual_kernel() {
    int w = (blockIdx.x * blockDim.x + threadIdx.x) >> 5;
    int lane = threadIdx.x & 31;
    if (w >= NN) return;
    int s, e; row_range(w, s, e);
    float2 a1 = make_float2(0.f, 0.f);
    float2 a2 = make_float2(0.f, 0.f);
    const __half2* __restrict__ p1 = reinterpret_cast<const __half2*>(g_P1h);
    const __half2* __restrict__ p2 = reinterpret_cast<const __half2*>(g_P2h);
    const int* __restrict__ cols = g_csr_col;
    const float* __restrict__ vals = g_csr_val;
    for (int base = s; base < e; base += 32) {
        int i = base + lane;
        int c = 0; float vv = 0.f;
        if (i < e) { c = cols[i]; vv = vals[i]; }
        int cnt = min(32, e - base);
        for (int j = 0; j < cnt; j++) {
            int   cc  = __shfl_sync(0xffffffffu, c, j);
            float val = __shfl_sync(0xffffffffu, vv, j);
            float2 f1 = __half22float2(p1[(size_t)cc * 32 + lane]);
            float2 f2 = __half22float2(p2[(size_t)cc * 32 + lane]);
            a1.x = fmaf(val, f1.x, a1.x);
            a1.y = fmaf(val, f1.y, a1.y);
            a2.x = fmaf(val, f2.x, a2.x);
            a2.y = fmaf(val, f2.y, a2.y);
        }
    }
    reinterpret_cast<float2*>(g_Q1)[(size_t)w * 32 + lane] = a1;
    reinterpret_cast<__half2*>(g_Q2h)[(size_t)w * 32 + lane] = __floats2half2_rn(a2.x, a2.y);
}

// out = 2 * (L @ Q2h) + P0 + Q1 - P2h + b2
__global__ void spmm_final_kernel(const float* __restrict__ b2,
                                  float* __restrict__ out) {
    int w = (blockIdx.x * blockDim.x + threadIdx.x) >> 5;
    int lane = threadIdx.x & 31;
    if (w >= NN) return;
    int s, e; row_range(w, s, e);
    float2 a = make_float2(0.f, 0.f);
    const __half2* __restrict__ q2 = reinterpret_cast<const __half2*>(g_Q2h);
    const int* __restrict__ cols = g_csr_col;
    const float* __restrict__ vals = g_csr_val;
    for (int base = s; base < e; base += 32) {
        int i = base + lane;
        int c = 0; float vv = 0.f;
        if (i < e) { c = cols[i]; vv = vals[i]; }
        int cnt = min(32, e - base);
        for (int j = 0; j < cnt; j++) {
            int   cc  = __shfl_sync(0xffffffffu, c, j);
            float val = __shfl_sync(0xffffffffu, vv, j);
            float2 f = __half22float2(q2[(size_t)cc * 32 + lane]);
            a.x = fmaf(val, f.x, a.x);
            a.y = fmaf(val, f.y, a.y);
        }
    }
    float2 p0 = reinterpret_cast<const float2*>(g_P0)[(size_t)w * 32 + lane];
    float2 q1 = reinterpret_cast<const float2*>(g_Q1)[(size_t)w * 32 + lane];
    float2 p2 = __half22float2(reinterpret_cast<const __half2*>(g_P2h)[(size_t)w * 32 + lane]);
    float2 bb = reinterpret_cast<const float2*>(b2)[lane];
    float2 r;
    r.x = 2.f * a.x + p0.x + q1.x - p2.x + bb.x;
    r.y = 2.f * a.y + p0.y + q1.y - p2.y + bb.y;
    reinterpret_cast<float2*>(out)[(size_t)w * 32 + lane] = r;
}

// ---------------- tensor-core GEMM machinery --------------------------------
#define MMA16816(d, a, b)                                                     \
    asm volatile(                                                             \
        "mma.sync.aligned.m16n8k16.row.col.f32.f16.f16.f32 "                  \
        "{%0,%1,%2,%3}, {%4,%5,%6,%7}, {%8,%9}, {%0,%1,%2,%3};"               \
        : "+f"((d)[0]), "+f"((d)[1]), "+f"((d)[2]), "+f"((d)[3])              \
        : "r"((a)[0]), "r"((a)[1]), "r"((a)[2]), "r"((a)[3]),                 \
          "r"((b)[0]), "r"((b)[1]))

__device__ __forceinline__ uint32_t s2u(const void* p) {
    return (uint32_t)__cvta_generic_to_shared(p);
}
__device__ __forceinline__ void cp16(uint32_t dst, const void* src, bool pred) {
    int sz = pred ? 16 : 0;
    asm volatile("cp.async.ca.shared.global [%0], [%1], 16, %2;\n"
                 :: "r"(dst), "l"(src), "r"(sz));
}
#define CP_COMMIT() asm volatile("cp.async.commit_group;\n" ::: "memory")
#define CP_WAIT1()  asm volatile("cp.async.wait_group 1;\n" ::: "memory")
#define CP_WAIT0()  asm volatile("cp.async.wait_group 0;\n" ::: "memory")

__device__ __forceinline__ void ldm_x4(uint32_t* r, uint32_t addr) {
    asm volatile("ldmatrix.sync.aligned.m8n8.x4.shared.b16 {%0,%1,%2,%3}, [%4];"
        : "=r"(r[0]), "=r"(r[1]), "=r"(r[2]), "=r"(r[3]) : "r"(addr));
}

// A smem layout: [128 rows][32 halves], 16B-chunk swizzle s = c ^ ((row>>1)&3)
// W smem layout: [64 n-rows][32 k-halves], same swizzle
#define A_SWZ(row, ch) (((ch) ^ (((row) >> 1) & 3)) * 8)

// unified GEMM core: M-tile 128, N-tile 64, BK 32, double-buffered cp.async
template <int CIN, int KT_COUNT, bool L1>
__device__ __forceinline__ void gemm_core(
    int m0, int n0, int tid,
    const __half* WH, int wstride,
    float acc[2][4][4]) {
    __shared__ __align__(16) __half Ash[2][128 * 32];
    __shared__ __align__(16) __half Asl[2][128 * 32];
    __shared__ __align__(16) __half Wsh[2][64 * 32];

    int lane = tid & 31, wid = tid >> 5;
    int wm = (wid & 3) * 32;
    int wn = (wid >> 2) * 32;

    auto stage = [&](int kt, int buf) {
        int k0 = kt * 32;
        const __half *Ah, *Al;
        int kc;
        if (L1) {
            int src = k0 >> 7;
            kc = k0 & 127;
            Ah = (src == 0) ? g_xh : ((src == 1) ? g_T1h : g_T2h);
            Al = (src == 0) ? g_xl : ((src == 1) ? g_T1l : g_T2l);
        } else {
            kc = k0;
            Ah = g_Hh;
            Al = g_Hl;
        }
        // A: 512 chunks of 8 halves (16B); 2 per thread
#pragma unroll
        for (int q = 0; q < 2; q++) {
            int ch = tid * 2 + q;
            int row = ch >> 2, cc = ch & 3;
            int gm = m0 + row;
            bool p = gm < NN;
            size_t off = (size_t)gm * CIN + kc + cc * 8;
            int sc = A_SWZ(row, cc);
            cp16(s2u(&Ash[buf][row * 32 + sc]), Ah + off, p);
            cp16(s2u(&Asl[buf][row * 32 + sc]), Al + off, p);
        }
        // W: read [k][n] row, scatter transposed into [n][k] with swizzle
        {
            int k = tid >> 3;              // 0..31
            int nb = (tid & 7) * 8;        // 0..56
            const __half* gw = WH + (size_t)(k0 + k) * wstride + n0 + nb;
            __half w[8];
            *reinterpret_cast<uint4*>(w) = *reinterpret_cast<const uint4*>(gw);
            int kch = k >> 3, kin = k & 7;
#pragma unroll
            for (int e2 = 0; e2 < 8; e2++) {
                int n = nb + e2;
                Wsh[buf][n * 32 + ((kch ^ ((n >> 1) & 3)) * 8) + kin] = w[e2];
            }
        }
    };

    stage(0, 0);
    CP_COMMIT();
    for (int kt = 0; kt < KT_COUNT; kt++) {
        int buf = kt & 1;
        if (kt + 1 < KT_COUNT) stage(kt + 1, buf ^ 1);
        CP_COMMIT();
        CP_WAIT1();
        __syncthreads();
#pragma unroll
        for (int kk = 0; kk < 2; kk++) {
            uint32_t afh[2][4], afl[2][4], bf[2][4];
#pragma unroll
            for (int i = 0; i < 2; i++) {
                int row = wm + i * 16 + (lane & 15);
                int chk = kk * 2 + (lane >> 4);
                uint32_t ad = s2u(&Ash[buf][row * 32 + A_SWZ(row, chk)]);
                ldm_x4(afh[i], ad);
                uint32_t al = s2u(&Asl[buf][row * 32 + A_SWZ(row, chk)]);
                ldm_x4(afl[i], al);
            }
#pragma unroll
            for (int jj = 0; jj < 2; jj++) {
                int n = wn + jj * 16 + ((lane >> 4) & 1) * 8 + (lane & 7);
                int chk = kk * 2 + ((lane >> 3) & 1);
                uint32_t bd = s2u(&Wsh[buf][n * 32 + ((chk ^ ((n >> 1) & 3)) * 8)]);
                ldm_x4(bf[jj], bd);
            }
#pragma unroll
            for (int i = 0; i < 2; i++)
#pragma unroll
                for (int j = 0; j < 4; j++) {
                    uint32_t* bb = &bf[j >> 1][(j & 1) * 2];
                    MMA16816(acc[i][j], afh[i], bb);
                    MMA16816(acc[i][j], afl[i], bb);
                }
        }
        __syncthreads();
    }
    CP_WAIT0();
}

// ---- layer 1: H(hi/lo) = relu([x|T1|T2] @ W1 + b1) -------------------------
__global__ __launch_bounds__(256) void gemm_l1_kernel(const float* __restrict__ bias) {
    int tid = threadIdx.x;
    int m0 = blockIdx.x * 128;
    int n0 = blockIdx.y * 64;
    int lane = tid & 31, wid = tid >> 5;
    int wm = (wid & 3) * 32, wn = (wid >> 2) * 32;
    int g = lane >> 2, c = lane & 3;

    float acc[2][4][4];
#pragma unroll
    for (int i = 0; i < 2; i++)
#pragma unroll
        for (int j = 0; j < 4; j++)
#pragma unroll
            for (int k = 0; k < 4; k++) acc[i][j][k] = 0.f;

    gemm_core<INC, KTOT1 / 32, true>(m0, n0, tid, g_W1h, HIDC, acc);

#pragma unroll
    for (int i = 0; i < 2; i++) {
#pragma unroll
        for (int j = 0; j < 4; j++) {
            int col = n0 + wn + j * 8 + 2 * c;
            float b0 = bias[col], b1v = bias[col + 1];
            int r0 = m0 + wm + i * 16 + g;
            int r1 = r0 + 8;
            float v0 = fmaxf(acc[i][j][0] + b0, 0.f);
            float v1 = fmaxf(acc[i][j][1] + b1v, 0.f);
            float v2 = fmaxf(acc[i][j][2] + b0, 0.f);
            float v3 = fmaxf(acc[i][j][3] + b1v, 0.f);
            if (r0 < NN) {
                __half h0, l0, h1, l1;
                split_h(v0, h0, l0); split_h(v1, h1, l1);
                size_t o = (size_t)r0 * HIDC + col;
                *reinterpret_cast<__half2*>(&g_Hh[o]) = __halves2half2(h0, h1);
                *reinterpret_cast<__half2*>(&g_Hl[o]) = __halves2half2(l0, l1);
            }
            if (r1 < NN) {
                __half h2, l2, h3, l3;
                split_h(v2, h2, l2); split_h(v3, h3, l3);
                size_t o = (size_t)r1 * HIDC + col;
                *reinterpret_cast<__half2*>(&g_Hh[o]) = __halves2half2(h2, h3);
                *reinterpret_cast<__half2*>(&g_Hl[o]) = __halves2half2(l2, l3);
            }
        }
    }
}

// ---- layer 2: P_y = H @ W2t[:, 64y:...] ------------------------------------
__global__ __launch_bounds__(256) void gemm_l2_kernel() {
    int tid = threadIdx.x;
    int m0 = blockIdx.x * 128;
    int y  = blockIdx.y;
    int n0 = y * 64;
    int lane = tid & 31, wid = tid >> 5;
    int wm = (wid & 3) * 32, wn = (wid >> 2) * 32;
    int g = lane >> 2, c = lane & 3;

    float acc[2][4][4];
#pragma unroll
    for (int i = 0; i < 2; i++)
#pragma unroll
        for (int j = 0; j < 4; j++)
#pragma unroll
            for (int k = 0; k < 4; k++) acc[i][j][k] = 0.f;

    gemm_core<HIDC, HIDC / 32, false>(m0, n0, tid, g_W2th, NTOT2, acc);

#pragma unroll
    for (int i = 0; i < 2; i++) {
#pragma unroll
        for (int j = 0; j < 4; j++) {
            int col = wn + j * 8 + 2 * c;
            int r0 = m0 + wm + i * 16 + g;
            int r1 = r0 + 8;
            if (r0 < NN) {
                size_t o = (size_t)r0 * OUTC + col;
                if (y == 0)
                    *reinterpret_cast<float2*>(&g_P0[o]) = make_float2(acc[i][j][0], acc[i][j][1]);
                else if (y == 1)
                    *reinterpret_cast<__half2*>(&g_P1h[o]) = __floats2half2_rn(acc[i][j][0], acc[i][j][1]);
                else
                    *reinterpret_cast<__half2*>(&g_P2h[o]) = __floats2half2_rn(acc[i][j][0], acc[i][j][1]);
            }
            if (r1 < NN) {
                size_t o = (size_t)r1 * OUTC + col;
                if (y == 0)
                    *reinterpret_cast<float2*>(&g_P0[o]) = make_float2(acc[i][j][2], acc[i][j][3]);
                else if (y == 1)
                    *reinterpret_cast<__half2*>(&g_P1h[o]) = __floats2half2_rn(acc[i][j][2], acc[i][j][3]);
                else
                    *reinterpret_cast<__half2*>(&g_P2h[o]) = __floats2half2_rn(acc[i][j][2], acc[i][j][3]);
            }
        }
    }
}

// ---------------- launch ----------------------------------------------------
extern "C" void kernel_launch(void* const* d_in, const int* in_sizes, int n_in,
                              void* d_out, int out_size) {
    const float* x  = nullptr; const void* ei = nullptr; const float* ew = nullptr;
    const float* W1 = nullptr; const float* b1 = nullptr;
    const float* W2 = nullptr; const float* b2 = nullptr;
    for (int i = 0; i < n_in; i++) {
        long long s = in_sizes[i];
        if      (s == (long long)NN * INC)        x  = (const float*)d_in[i];
        else if (s == 2LL * EE)                   ei = d_in[i];
        else if (s == (long long)EE)              ew = (const float*)d_in[i];
        else if (s == 3LL * INC * HIDC)           W1 = (const float*)d_in[i];
        else if (s == (long long)HIDC)            b1 = (const float*)d_in[i];
        else if (s == 3LL * HIDC * OUTC)          W2 = (const float*)d_in[i];
        else if (s == (long long)OUTC)            b2 = (const float*)d_in[i];
    }
    if (!x)  x  = (const float*)d_in[0];
    if (!ei) ei = d_in[1];
    if (!ew) ew = (const float*)d_in[2];
    if (!W1) W1 = (const float*)d_in[3];
    if (!b1) b1 = (const float*)d_in[4];
    if (!W2) W2 = (const float*)d_in[5];
    if (!b2) b2 = (const float*)d_in[6];
    float* out = (float*)d_out;

    int nb = (NN + 255) / 256;
    int eb = (EE + 255) / 256;

    detect_kernel<<<1, 32>>>((const long long*)ei);
    zero_kernel<<<nb, 256>>>();
    x2h_kernel<<<(NN * INC + 255) / 256, 256>>>(x);
    w1h_kernel<<<(KTOT1 * HIDC + 255) / 256, 256>>>(W1);
    w2th_kernel<<<(3 * HIDC * OUTC + 255) / 256, 256>>>(W2);
    deg_count_kernel<<<eb, 256>>>(ei, ew);
    dinv_kernel<<<nb, 256>>>();
    scan_local_kernel<<<SCAN_BLOCKS, 256>>>();
    scan_blocks_kernel<<<1, 128>>>();
    scan_add_kernel<<<SCAN_BLOCKS, 256>>>();
    scatter_kernel<<<eb, 256>>>(ei, ew);

    int sg = (NN * 32 + 255) / 256;  // warp per row

    // ---- layer 1 ----
    spmm1_kernel<<<sg, 256>>>();
    spmm2_kernel<<<sg, 256>>>(x);
    dim3 g1((NN + 127) / 128, HIDC / 64);
    gemm_l1_kernel<<<g1, 256>>>(b1);

    // ---- layer 2 (commuted; fp16 gathers) ----
    dim3 g2((NN + 127) / 128, 3);
    gemm_l2_kernel<<<g2, 256>>>();
    spmm_dual_kernel<<<sg, 256>>>();
    spmm_final_kernel<<<sg, 256>>>(b2, out);
}